// round 12
// baseline (speedup 1.0000x reference)
#include <cuda_runtime.h>
#include <cuda_bf16.h>
#include <math.h>
#include <stdint.h>

// Problem constants
#define BB 128
#define TT 512
#define DD 512
#define HH 512
#define G4 2048
#define NR (BB*TT)
#define AA 32

typedef __nv_bfloat16 bf16;

// ---------------- scratch (device globals) ----------------
__device__ float g_Gpi[(size_t)NR * G4];
__device__ float g_Gvf[(size_t)NR * G4];
__device__ float g_Z2pi[(size_t)NR * HH];
__device__ float g_Z2vf[(size_t)NR * HH];
__device__ unsigned g_bar_count4[4];
__device__ unsigned g_bar_gen4[4];

// bf16 hi/lo pairs
__device__ __align__(16) bf16 g_feat_h[(size_t)NR * DD];
__device__ __align__(16) bf16 g_feat_l[(size_t)NR * DD];
__device__ __align__(16) bf16 g_ypi_h[(size_t)NR * HH];
__device__ __align__(16) bf16 g_ypi_l[(size_t)NR * HH];
__device__ __align__(16) bf16 g_yvf_h[(size_t)NR * HH];
__device__ __align__(16) bf16 g_yvf_l[(size_t)NR * HH];
__device__ __align__(16) bf16 g_z1p_h[(size_t)NR * HH];
__device__ __align__(16) bf16 g_z1p_l[(size_t)NR * HH];
__device__ __align__(16) bf16 g_z1v_h[(size_t)NR * HH];
__device__ __align__(16) bf16 g_z1v_l[(size_t)NR * HH];
// h ping-pong: [lstm][pingpong][128][512], bf16 hi/lo (pre-masked for the consuming step)
__device__ __align__(16) bf16 g_hh[2 * 2 * BB * HH];
__device__ __align__(16) bf16 g_hl[2 * 2 * BB * HH];
// weights blob
#define WOFF_IHPI 0
#define WOFF_IHVF 1048576
#define WOFF_PW1  2097152
#define WOFF_PW2  2359296
#define WOFF_VW1  2621440
#define WOFF_VW2  2883584
#define WTOT      3145728
__device__ __align__(16) bf16 g_w_h[WTOT];
__device__ __align__(16) bf16 g_w_l[WTOT];

__device__ __forceinline__ float sigf(float x) {
    return __fdividef(1.0f, 1.0f + __expf(-x));
}
__device__ __forceinline__ float ftanh(float x) {
    float e = __expf(2.0f * x);
    return 1.0f - __fdividef(2.0f, e + 1.0f);
}

// ---------------- PTX helpers ----------------
#define CP16(d, s) asm volatile("cp.async.cg.shared.global [%0], [%1], 16;" :: "r"(d), "l"(s) : "memory")
#define CP_COMMIT() asm volatile("cp.async.commit_group;" ::: "memory")
#define CP_WAIT0()  asm volatile("cp.async.wait_group 0;" ::: "memory")
#define CP_WAIT1()  asm volatile("cp.async.wait_group 1;" ::: "memory")
#define CP_WAIT2()  asm volatile("cp.async.wait_group 2;" ::: "memory")

__device__ __forceinline__ uint32_t smem_u32(const void* p) {
    uint32_t a;
    asm("{ .reg .u64 t; cvta.to.shared.u64 t, %1; cvt.u32.u64 %0, t; }" : "=r"(a) : "l"(p));
    return a;
}

#define MMA16816(c, a, b) \
    asm volatile("mma.sync.aligned.m16n8k16.row.col.f32.bf16.bf16.f32 " \
        "{%0,%1,%2,%3}, {%4,%5,%6,%7}, {%8,%9}, {%0,%1,%2,%3};" \
        : "+f"((c)[0]), "+f"((c)[1]), "+f"((c)[2]), "+f"((c)[3]) \
        : "r"((a)[0]), "r"((a)[1]), "r"((a)[2]), "r"((a)[3]), "r"((b)[0]), "r"((b)[1]))

#define LDSM4(r0, r1, r2, r3, addr) \
    asm volatile("ldmatrix.sync.aligned.m8n8.x4.shared.b16 {%0,%1,%2,%3}, [%4];" \
        : "=r"(r0), "=r"(r1), "=r"(r2), "=r"(r3) : "r"(addr))
#define LDSM2(r0, r1, addr) \
    asm volatile("ldmatrix.sync.aligned.m8n8.x2.shared.b16 {%0,%1}, [%2];" \
        : "=r"(r0), "=r"(r1) : "r"(addr))

// ---------------- fp32 -> bf16 hi/lo converters ----------------
__device__ __forceinline__ void cvt_one(const float* __restrict__ x,
                                        bf16* __restrict__ hi, bf16* __restrict__ lo, size_t i)
{
    float4 v = ((const float4*)x)[i];
    bf16 h0 = __float2bfloat16_rn(v.x), h1 = __float2bfloat16_rn(v.y);
    bf16 h2 = __float2bfloat16_rn(v.z), h3 = __float2bfloat16_rn(v.w);
    bf16 l0 = __float2bfloat16_rn(v.x - __bfloat162float(h0));
    bf16 l1 = __float2bfloat16_rn(v.y - __bfloat162float(h1));
    bf16 l2 = __float2bfloat16_rn(v.z - __bfloat162float(h2));
    bf16 l3 = __float2bfloat16_rn(v.w - __bfloat162float(h3));
    __nv_bfloat162 hp0; hp0.x = h0; hp0.y = h1;
    __nv_bfloat162 hp1; hp1.x = h2; hp1.y = h3;
    __nv_bfloat162 lp0; lp0.x = l0; lp0.y = l1;
    __nv_bfloat162 lp1; lp1.x = l2; lp1.y = l3;
    ((__nv_bfloat162*)hi)[2 * i]     = hp0;
    ((__nv_bfloat162*)hi)[2 * i + 1] = hp1;
    ((__nv_bfloat162*)lo)[2 * i]     = lp0;
    ((__nv_bfloat162*)lo)[2 * i + 1] = lp1;
}

__global__ __launch_bounds__(256) void cvt_pair(const float* __restrict__ x,
                                                bf16* __restrict__ hi, bf16* __restrict__ lo, size_t n4)
{
    for (size_t i = blockIdx.x * blockDim.x + threadIdx.x; i < n4; i += (size_t)gridDim.x * blockDim.x)
        cvt_one(x, hi, lo, i);
}

__global__ __launch_bounds__(256) void cvt3(
    const float* __restrict__ x0, bf16* __restrict__ h0, bf16* __restrict__ l0, size_t n0,
    const float* __restrict__ x1, bf16* __restrict__ h1, bf16* __restrict__ l1, size_t n1,
    const float* __restrict__ x2, bf16* __restrict__ h2, bf16* __restrict__ l2, size_t n2)
{
    size_t tot = n0 + n1 + n2;
    for (size_t i = blockIdx.x * blockDim.x + threadIdx.x; i < tot; i += (size_t)gridDim.x * blockDim.x) {
        if (i < n0) cvt_one(x0, h0, l0, i);
        else if (i < n0 + n1) cvt_one(x1, h1, l1, i - n0);
        else cvt_one(x2, h2, l2, i - n0 - n1);
    }
}

// ---------------- HMMA bf16-split GEMM (R10, unchanged) ----------------
#define KSTG 32
#define ROWP 40
#define MATB (128 * ROWP)
#define STGB (4 * MATB)
__global__ __launch_bounds__(256, 1) void tgemm(
    const bf16* __restrict__ Ah, const bf16* __restrict__ Al,
    const bf16* __restrict__ Wh, const bf16* __restrict__ Wl,
    const float* __restrict__ b1, const float* __restrict__ b2,
    float* __restrict__ C, bf16* __restrict__ Ch, bf16* __restrict__ Cl,
    int N, int relu)
{
    extern __shared__ bf16 smbf[];
    const int tid  = threadIdx.x;
    const int wid  = tid >> 5, lane = tid & 31;
    const int g    = lane >> 2, tig = lane & 3;
    const int m0   = (wid & 3) * 32;
    const int n0   = (wid >> 2) * 64;
    const size_t arow0 = (size_t)blockIdx.y * 128;
    const size_t brow0 = (size_t)blockIdx.x * 128;

    const int a_lrow = ((lane >> 3) & 1) * 8 + (lane & 7);
    const int a_kof  = (lane >> 4) * 8;
    const int b_lrow = lane & 7;
    const int b_kof  = ((lane >> 3) & 1) * 8;

    const int lmat = tid >> 6, t64 = tid & 63;
    const bf16* gsrc;
    if      (lmat == 0) gsrc = Ah + arow0 * 512;
    else if (lmat == 1) gsrc = Al + arow0 * 512;
    else if (lmat == 2) gsrc = Wh + brow0 * 512;
    else                gsrc = Wl + brow0 * 512;
    const uint32_t sbase = smem_u32(smbf);
    const uint32_t sdstm = sbase + (uint32_t)lmat * (MATB * 2);

    float acc[2][8][4];
#pragma unroll
    for (int i = 0; i < 2; i++)
#pragma unroll
        for (int j = 0; j < 8; j++)
#pragma unroll
            for (int q = 0; q < 4; q++) acc[i][j][q] = 0.0f;

#pragma unroll
    for (int s = 0; s < 2; s++) {
        const uint32_t db = sdstm + (uint32_t)s * (STGB * 2);
        const int k0 = s * KSTG;
#pragma unroll
        for (int i = 0; i < 8; i++) {
            int idx = i * 64 + t64;
            int row = idx >> 2, gg = idx & 3;
            CP16(db + (uint32_t)row * (ROWP * 2) + (uint32_t)gg * 16,
                 gsrc + (size_t)row * 512 + k0 + gg * 8);
        }
        CP_COMMIT();
    }

    const int NSTG = 512 / KSTG;
#pragma unroll 1
    for (int c = 0; c < NSTG; c++) {
        if (c < NSTG - 2) { CP_WAIT1(); } else { CP_WAIT0(); }
        __syncthreads();
        const uint32_t sS = sbase + (uint32_t)(c & 1) * (STGB * 2);
        const uint32_t sAh_u = sS;
        const uint32_t sAl_u = sS + MATB * 2;
        const uint32_t sWh_u = sS + 2 * MATB * 2;
        const uint32_t sWl_u = sS + 3 * MATB * 2;
#pragma unroll
        for (int kk = 0; kk < KSTG; kk += 16) {
            uint32_t ah[2][4], al[2][4];
#pragma unroll
            for (int tm = 0; tm < 2; tm++) {
                uint32_t aoff = (uint32_t)((m0 + tm * 16 + a_lrow) * ROWP + kk + a_kof) * 2;
                LDSM4(ah[tm][0], ah[tm][1], ah[tm][2], ah[tm][3], sAh_u + aoff);
                LDSM4(al[tm][0], al[tm][1], al[tm][2], al[tm][3], sAl_u + aoff);
            }
            uint32_t bh[8][2], bl[8][2];
#pragma unroll
            for (int tn = 0; tn < 8; tn++) {
                uint32_t boff = (uint32_t)((n0 + tn * 8 + b_lrow) * ROWP + kk + b_kof) * 2;
                LDSM2(bh[tn][0], bh[tn][1], sWh_u + boff);
                LDSM2(bl[tn][0], bl[tn][1], sWl_u + boff);
            }
#pragma unroll
            for (int tm = 0; tm < 2; tm++)
#pragma unroll
                for (int tn = 0; tn < 8; tn++) {
                    MMA16816(acc[tm][tn], ah[tm], bh[tn]);
                    MMA16816(acc[tm][tn], ah[tm], bl[tn]);
                    MMA16816(acc[tm][tn], al[tm], bh[tn]);
                }
        }
        __syncthreads();
        if (c + 2 < NSTG) {
            const uint32_t db = sdstm + (uint32_t)(c & 1) * (STGB * 2);
            const int k0 = (c + 2) * KSTG;
#pragma unroll
            for (int i = 0; i < 8; i++) {
                int idx = i * 64 + t64;
                int row = idx >> 2, gg = idx & 3;
                CP16(db + (uint32_t)row * (ROWP * 2) + (uint32_t)gg * 16,
                     gsrc + (size_t)row * 512 + k0 + gg * 8);
            }
            CP_COMMIT();
        }
    }

#pragma unroll
    for (int tn = 0; tn < 8; tn++) {
        int cc = (int)brow0 + n0 + tn * 8 + 2 * tig;
        float bv0 = b1[cc]     + (b2 ? b2[cc]     : 0.0f);
        float bv1 = b1[cc + 1] + (b2 ? b2[cc + 1] : 0.0f);
#pragma unroll
        for (int tm = 0; tm < 2; tm++) {
            size_t r0 = arow0 + m0 + tm * 16 + g;
            float v[4];
            v[0] = acc[tm][tn][0] + bv0;
            v[1] = acc[tm][tn][1] + bv1;
            v[2] = acc[tm][tn][2] + bv0;
            v[3] = acc[tm][tn][3] + bv1;
            if (relu) {
#pragma unroll
                for (int q = 0; q < 4; q++) v[q] = fmaxf(v[q], 0.f);
            }
            if (Ch) {
                __nv_bfloat162 h0, h1, l0, l1;
                h0.x = __float2bfloat16_rn(v[0]); h0.y = __float2bfloat16_rn(v[1]);
                h1.x = __float2bfloat16_rn(v[2]); h1.y = __float2bfloat16_rn(v[3]);
                l0.x = __float2bfloat16_rn(v[0] - __bfloat162float(h0.x));
                l0.y = __float2bfloat16_rn(v[1] - __bfloat162float(h0.y));
                l1.x = __float2bfloat16_rn(v[2] - __bfloat162float(h1.x));
                l1.y = __float2bfloat16_rn(v[3] - __bfloat162float(h1.y));
                *(__nv_bfloat162*)(Ch + r0 * (size_t)N + cc)       = h0;
                *(__nv_bfloat162*)(Cl + r0 * (size_t)N + cc)       = l0;
                *(__nv_bfloat162*)(Ch + (r0 + 8) * (size_t)N + cc) = h1;
                *(__nv_bfloat162*)(Cl + (r0 + 8) * (size_t)N + cc) = l1;
            } else {
                *(float2*)(C + r0 * (size_t)N + cc)       = make_float2(v[0], v[1]);
                *(float2*)(C + (r0 + 8) * (size_t)N + cc) = make_float2(v[2], v[3]);
            }
        }
    }
}

// ---------------- per-group software barrier (32 CTAs per group) ----------------
__device__ __forceinline__ void grid_bar_grp(int grp, int nct) {
    __threadfence();
    __syncthreads();
    if (threadIdx.x == 0) {
        volatile unsigned* vgen = &g_bar_gen4[grp];
        unsigned g = *vgen;
        unsigned a = atomicAdd(&g_bar_count4[grp], 1u);
        if (a == (unsigned)nct - 1u) {
            g_bar_count4[grp] = 0u;
            __threadfence();
            atomicAdd(&g_bar_gen4[grp], 1u);
        } else {
            while (*vgen == g) { }
        }
        __threadfence();
    }
    __syncthreads();
}

// ---------------- persistent recurrent kernel: 4-deep cp.async pipeline ----------------
#define RPAD 72
#define WPAD 520
#define SGPAD 72
#define HBUF (64 * RPAD * 2)
#define OFF_WH   0
#define OFF_WL   (64 * WPAD * 2)
#define OFF_HH0  (2 * 64 * WPAD * 2)
#define OFF_HL0  (OFF_HH0 + 4 * HBUF)
#define OFF_SG   (OFF_HL0 + 4 * HBUF)
#define OFF_MASK (OFF_SG + 64 * SGPAD * 4)
#define OFF_SC   (OFF_MASK + 128 * 4)
#define LSTM_SMEM (OFF_SC + 64 * 16 * 4)

__global__ __launch_bounds__(256, 1) void lstm_recur(
    const float* __restrict__ Gpi, const float* __restrict__ Gvf,
    const float* __restrict__ starts,
    const float* __restrict__ h0pi, const float* __restrict__ c0pi,
    const float* __restrict__ h0vf, const float* __restrict__ c0vf,
    const float* __restrict__ Whhpi, const float* __restrict__ Whhvf,
    bf16* __restrict__ Yph, bf16* __restrict__ Ypl,
    bf16* __restrict__ Yvh, bf16* __restrict__ Yvl,
    bf16* __restrict__ hhg, bf16* __restrict__ hlg,
    float* __restrict__ out)
{
    extern __shared__ char sm8[];
    bf16*  sWh = (bf16*)(sm8 + OFF_WH);
    bf16*  sWl = (bf16*)(sm8 + OFF_WL);
    float* sg  = (float*)(sm8 + OFF_SG);
    float* smk = (float*)(sm8 + OFF_MASK);
    float* sc  = (float*)(sm8 + OFF_SC);

    const int ct   = blockIdx.x;
    const int lstm = ct >> 6;
    const int grp  = ct >> 5;
    const int b0   = ((ct >> 5) & 1) * 64;
    const int cid  = ct & 31;
    const int hc0  = cid * 16;
    const int tx   = threadIdx.x;
    const int wid  = tx >> 5, lane = tx & 31;
    const int g    = lane >> 2, tig = lane & 3;
    const int m0w  = (wid & 1) * 32;
    const int n0w  = (wid >> 1) * 16;

    const int a_lrow = ((lane >> 3) & 1) * 8 + (lane & 7);
    const int a_kof  = (lane >> 4) * 8;
    const int b_lrow = lane & 7;
    const int b_kof  = ((lane >> 3) & 1) * 8;

    const float* Gx  = lstm ? Gvf   : Gpi;
    const float* Whh = lstm ? Whhvf : Whhpi;
    const float* h0  = lstm ? h0vf  : h0pi;
    const float* c0  = lstm ? c0vf  : c0pi;
    bf16* Yh = lstm ? Yvh : Yph;
    bf16* Yl = lstm ? Yvl : Ypl;
    bf16* hhb = hhg + lstm * 2 * BB * HH;
    bf16* hlb = hlg + lstm * 2 * BB * HH;

    const uint32_t sb = smem_u32(sm8);
    uint32_t shh[4], shl[4];
#pragma unroll
    for (int i = 0; i < 4; i++) {
        shh[i] = sb + OFF_HH0 + (uint32_t)i * HBUF;
        shl[i] = sb + OFF_HL0 + (uint32_t)i * HBUF;
    }
    const uint32_t sWh_u = sb + OFF_WH;
    const uint32_t sWl_u = sb + OFF_WL;

    // load + split Whh slice
    for (int s = 0; s < 128; s++) {
        int idx = tx + s * 256;
        int j = idx >> 9, k = idx & 511;
        int gc = ((j >> 4) << 9) + hc0 + (j & 15);
        float w = Whh[(size_t)gc * HH + k];
        bf16 hi = __float2bfloat16_rn(w);
        sWh[j * WPAD + k] = hi;
        sWl[j * WPAD + k] = __float2bfloat16_rn(w - __bfloat162float(hi));
    }
    // init c and h0 (ping 0, pre-masked, bf16 split)
    for (int s = 0; s < 4; s++) {
        int idx = tx + s * 256;
        int br = idx >> 4, q = idx & 15;
        int b = b0 + br;
        sc[br * 16 + q] = c0[b * HH + hc0 + q];
        float m0 = 1.0f - starts[b * TT];
        float v = h0[b * HH + hc0 + q] * m0;
        bf16 hi = __float2bfloat16_rn(v);
        hhb[b * HH + hc0 + q] = hi;
        hlb[b * HH + hc0 + q] = __float2bfloat16_rn(v - __bfloat162float(hi));
    }
    grid_bar_grp(grp, 32);

    const int ebr = tx >> 2;
    const int ekb = (tx & 3) << 2;
    const int eb  = b0 + ebr;

    for (int t = 0; t < TT; t++) {
        const int cur = t & 1;
        const bf16* hcH = hhb + cur * BB * HH;
        const bf16* hcL = hlb + cur * BB * HH;

        // stage one 64-k chunk of h into buffer bufi (4 granules/thread) + commit
        auto stage_chunk = [&](int cn, int bufi) {
            const uint32_t dh = shh[bufi], dl = shl[bufi];
            const int kc = cn * 64;
#pragma unroll
            for (int i = 0; i < 4; i++) {
                int idx = tx + i * 256;
                int m = idx >> 9;
                int g512 = idx & 511;
                int row = g512 >> 3, gg = g512 & 7;
                uint32_t so = (uint32_t)row * (RPAD * 2) + (uint32_t)gg * 16;
                size_t  go = (size_t)(b0 + row) * 512 + kc + gg * 8;
                if (m) CP16(dl + so, hcL + go);
                else   CP16(dh + so, hcH + go);
            }
            CP_COMMIT();
        };

        // G prefetch for this step (hidden behind MMA loop)
        const size_t grow = ((size_t)eb * TT + t) * G4 + hc0 + ekb;
        const float4 pgi = *(const float4*)(Gx + grow);
        const float4 pgf = *(const float4*)(Gx + grow + 512);
        const float4 pgg = *(const float4*)(Gx + grow + 1024);
        const float4 pgo = *(const float4*)(Gx + grow + 1536);

        // prologue: stage chunks 0,1,2
        stage_chunk(0, 0);
        stage_chunk(1, 1);
        stage_chunk(2, 2);

        // masks
        if (tx < 64) smk[tx] = 1.0f - starts[(b0 + tx) * TT + t];
        else if (tx < 128) {
            int br = tx - 64;
            smk[64 + br] = (t + 1 < TT) ? (1.0f - starts[(b0 + br) * TT + t + 1]) : 1.0f;
        }

        float acc[2][2][4], accB[2][2][4];
#pragma unroll
        for (int tm = 0; tm < 2; tm++)
#pragma unroll
            for (int tn = 0; tn < 2; tn++)
#pragma unroll
                for (int q = 0; q < 4; q++) { acc[tm][tn][q] = 0.0f; accB[tm][tn][q] = 0.0f; }

#pragma unroll 1
        for (int c = 0; c < 8; c++) {
            // ensure chunk c complete (committed groups: min(c+3,8); need c+1 done)
            if (c < 6) { CP_WAIT2(); } else if (c == 6) { CP_WAIT1(); } else { CP_WAIT0(); }
            __syncthreads();   // single sync per chunk: also proves compute c-1 done by all
            const int buf = c & 3;
            const uint32_t Sh_u = shh[buf];
            const uint32_t Sl_u = shl[buf];
#pragma unroll
            for (int k16 = 0; k16 < 64; k16 += 16) {
                uint32_t ah[2][4], al[2][4];
#pragma unroll
                for (int tm = 0; tm < 2; tm++) {
                    uint32_t aoff = (uint32_t)((m0w + tm * 16 + a_lrow) * RPAD + k16 + a_kof) * 2;
                    LDSM4(ah[tm][0], ah[tm][1], ah[tm][2], ah[tm][3], Sh_u + aoff);
                    LDSM4(al[tm][0], al[tm][1], al[tm][2], al[tm][3], Sl_u + aoff);
                }
                const int kglob = c * 64 + k16 + b_kof;
                uint32_t bh[2][2], bl[2][2];
#pragma unroll
                for (int tn = 0; tn < 2; tn++) {
                    uint32_t boff = (uint32_t)((n0w + tn * 8 + b_lrow) * WPAD + kglob) * 2;
                    LDSM2(bh[tn][0], bh[tn][1], sWh_u + boff);
                    LDSM2(bl[tn][0], bl[tn][1], sWl_u + boff);
                }
#pragma unroll
                for (int tm = 0; tm < 2; tm++)
#pragma unroll
                    for (int tn = 0; tn < 2; tn++) {
                        MMA16816(acc[tm][tn],  ah[tm], bh[tn]);
                        MMA16816(accB[tm][tn], ah[tm], bl[tn]);
                        MMA16816(accB[tm][tn], al[tm], bh[tn]);
                    }
            }
            // stage chunk c+3 into buffer (c+3)&3 = (c-1)&3: all threads are past
            // sync_c, hence finished compute c-1 -> its buffer is reusable.
            if (c + 3 < 8) stage_chunk(c + 3, (c + 3) & 3);
        }

        // publish gate preactivations (h-part): acc + accB
        __syncthreads();    // compute chunk 7 done by all before sg writes are consumed below
#pragma unroll
        for (int tm = 0; tm < 2; tm++)
#pragma unroll
            for (int tn = 0; tn < 2; tn++) {
                int r = m0w + 16 * tm + g;
                int c0i = n0w + tn * 8 + 2 * tig;
                *(float2*)&sg[r * SGPAD + c0i] =
                    make_float2(acc[tm][tn][0] + accB[tm][tn][0], acc[tm][tn][1] + accB[tm][tn][1]);
                *(float2*)&sg[(r + 8) * SGPAD + c0i] =
                    make_float2(acc[tm][tn][2] + accB[tm][tn][2], acc[tm][tn][3] + accB[tm][tn][3]);
            }
        __syncthreads();

        // elementwise update
        {
            const float mcur = smk[ebr];
            const float mnxt = smk[64 + ebr];
            const float gi_[4] = {pgi.x, pgi.y, pgi.z, pgi.w};
            const float gf_[4] = {pgf.x, pgf.y, pgf.z, pgf.w};
            const float gg_[4] = {pgg.x, pgg.y, pgg.z, pgg.w};
            const float go_[4] = {pgo.x, pgo.y, pgo.z, pgo.w};
            float hn[4];
#pragma unroll
            for (int i = 0; i < 4; i++) {
                int q = ekb + i;
                float vi = sg[ebr * SGPAD + q]      + gi_[i];
                float vf = sg[ebr * SGPAD + 16 + q] + gf_[i];
                float vg = sg[ebr * SGPAD + 32 + q] + gg_[i];
                float vo = sg[ebr * SGPAD + 48 + q] + go_[i];
                float cc = sc[ebr * 16 + q] * mcur;
                float cn = sigf(vf) * cc + sigf(vi) * ftanh(vg);
                hn[i] = sigf(vo) * ftanh(cn);
                sc[ebr * 16 + q] = cn;
            }
            // Y (unmasked) bf16 split
            {
                size_t yo = ((size_t)eb * TT + t) * HH + hc0 + ekb;
                __nv_bfloat162 h01, h23, l01, l23;
                h01.x = __float2bfloat16_rn(hn[0]); h01.y = __float2bfloat16_rn(hn[1]);
                h23.x = __float2bfloat16_rn(hn[2]); h23.y = __float2bfloat16_rn(hn[3]);
                l01.x = __float2bfloat16_rn(hn[0] - __bfloat162float(h01.x));
                l01.y = __float2bfloat16_rn(hn[1] - __bfloat162float(h01.y));
                l23.x = __float2bfloat16_rn(hn[2] - __bfloat162float(h23.x));
                l23.y = __float2bfloat16_rn(hn[3] - __bfloat162float(h23.y));
                *(__nv_bfloat162*)(Yh + yo)     = h01;
                *(__nv_bfloat162*)(Yh + yo + 2) = h23;
                *(__nv_bfloat162*)(Yl + yo)     = l01;
                *(__nv_bfloat162*)(Yl + yo + 2) = l23;
            }
            if (t + 1 < TT) {
                bf16* hnH = hhb + ((t + 1) & 1) * BB * HH;
                bf16* hnL = hlb + ((t + 1) & 1) * BB * HH;
                size_t ho = (size_t)eb * HH + hc0 + ekb;
                __nv_bfloat162 h01, h23, l01, l23;
                float v0 = hn[0] * mnxt, v1 = hn[1] * mnxt, v2 = hn[2] * mnxt, v3 = hn[3] * mnxt;
                h01.x = __float2bfloat16_rn(v0); h01.y = __float2bfloat16_rn(v1);
                h23.x = __float2bfloat16_rn(v2); h23.y = __float2bfloat16_rn(v3);
                l01.x = __float2bfloat16_rn(v0 - __bfloat162float(h01.x));
                l01.y = __float2bfloat16_rn(v1 - __bfloat162float(h01.y));
                l23.x = __float2bfloat16_rn(v2 - __bfloat162float(h23.x));
                l23.y = __float2bfloat16_rn(v3 - __bfloat162float(h23.y));
                *(__nv_bfloat162*)(hnH + ho)     = h01;
                *(__nv_bfloat162*)(hnH + ho + 2) = h23;
                *(__nv_bfloat162*)(hnL + ho)     = l01;
                *(__nv_bfloat162*)(hnL + ho + 2) = l23;
            } else {
                float* oh = out + (size_t)3 * NR + (size_t)lstm * 2 * NR;
#pragma unroll
                for (int i = 0; i < 4; i++)
                    oh[eb * HH + hc0 + ekb + i] = hn[i];
            }
        }
        grid_bar_grp(grp, 32);
    }

    // final c -> out
    float* oc = out + (size_t)3 * NR + (size_t)lstm * 2 * NR + NR;
    for (int s = 0; s < 4; s++) {
        int idx = tx + s * 256;
        int br = idx >> 4, q = idx & 15;
        oc[(b0 + br) * HH + hc0 + q] = sc[br * 16 + q];
    }
}

// ---------------- heads ----------------
__global__ __launch_bounds__(128) void head_kernel(
    const float* __restrict__ Zpi, const float* __restrict__ Zvf,
    const float* __restrict__ aw, const float* __restrict__ ab,
    const float* __restrict__ cw, const float* __restrict__ cb,
    float* __restrict__ out)
{
    __shared__ float sx[512];
    __shared__ float slog[32];
    __shared__ float sval[4];
    const int n  = blockIdx.x;
    const int tx = threadIdx.x;

    ((float4*)sx)[tx] = ((const float4*)(Zpi + (size_t)n * 512))[tx];

    float4 xv = ((const float4*)(Zvf + (size_t)n * 512))[tx];
    float4 wv = ((const float4*)cw)[tx];
    float v = xv.x * wv.x + xv.y * wv.y + xv.z * wv.z + xv.w * wv.w;
#pragma unroll
    for (int off = 16; off; off >>= 1) v += __shfl_xor_sync(0xffffffffu, v, off);
    if ((tx & 31) == 0) sval[tx >> 5] = v;
    __syncthreads();

    const int l = tx >> 2;
    const int part = tx & 3;
    const float* wl = aw + l * 512 + part * 128;
    const float* xl = sx + part * 128;
    float s = 0.0f;
#pragma unroll 8
    for (int k4 = 0; k4 < 32; k4++) {
        float4 a = ((const float4*)xl)[k4];
        float4 w = ((const float4*)wl)[k4];
        s += a.x * w.x + a.y * w.y + a.z * w.z + a.w * w.w;
    }
    s += __shfl_xor_sync(0xffffffffu, s, 1);
    s += __shfl_xor_sync(0xffffffffu, s, 2);
    if (part == 0) slog[l] = s + ab[l];
    __syncthreads();

    if (tx < 32) {
        float lv = slog[tx];
        float m = lv; int mi = tx;
#pragma unroll
        for (int off = 16; off; off >>= 1) {
            float om = __shfl_xor_sync(0xffffffffu, m, off);
            int   oi = __shfl_xor_sync(0xffffffffu, mi, off);
            if (om > m || (om == m && oi < mi)) { m = om; mi = oi; }
        }
        float e = __expf(lv - m);
#pragma unroll
        for (int off = 16; off; off >>= 1) e += __shfl_xor_sync(0xffffffffu, e, off);
        if (tx == 0) {
            out[n] = (float)mi;
            out[(size_t)NR + n] = sval[0] + sval[1] + sval[2] + sval[3] + cb[0];
            out[(size_t)2 * NR + n] = -__logf(e);
        }
    }
}

// ---------------- launch ----------------
extern "C" void kernel_launch(void* const* d_in, const int* in_sizes, int n_in,
                              void* d_out, int out_size)
{
    const float* features = (const float*)d_in[0];
    const float* starts   = (const float*)d_in[1];
    const float* h0pi = (const float*)d_in[2];
    const float* c0pi = (const float*)d_in[3];
    const float* h0vf = (const float*)d_in[4];
    const float* c0vf = (const float*)d_in[5];
    const float* Wihpi = (const float*)d_in[6];
    const float* Whhpi = (const float*)d_in[7];
    const float* bihpi = (const float*)d_in[8];
    const float* bhhpi = (const float*)d_in[9];
    const float* Wihvf = (const float*)d_in[10];
    const float* Whhvf = (const float*)d_in[11];
    const float* bihvf = (const float*)d_in[12];
    const float* bhhvf = (const float*)d_in[13];
    const float* polw1 = (const float*)d_in[14];
    const float* polb1 = (const float*)d_in[15];
    const float* polw2 = (const float*)d_in[16];
    const float* polb2 = (const float*)d_in[17];
    const float* valw1 = (const float*)d_in[18];
    const float* valb1 = (const float*)d_in[19];
    const float* valw2 = (const float*)d_in[20];
    const float* valb2 = (const float*)d_in[21];
    const float* aw = (const float*)d_in[22];
    const float* ab = (const float*)d_in[23];
    const float* cw = (const float*)d_in[24];
    const float* cb = (const float*)d_in[25];

    float *Gpi, *Gvf, *Z2pi, *Z2vf;
    cudaGetSymbolAddress((void**)&Gpi,  g_Gpi);
    cudaGetSymbolAddress((void**)&Gvf,  g_Gvf);
    cudaGetSymbolAddress((void**)&Z2pi, g_Z2pi);
    cudaGetSymbolAddress((void**)&Z2vf, g_Z2vf);
    bf16 *fh, *fl, *yph, *ypl, *yvh, *yvl, *z1ph, *z1pl, *z1vh, *z1vl, *wh, *wlp, *hh, *hl;
    cudaGetSymbolAddress((void**)&fh,  g_feat_h);
    cudaGetSymbolAddress((void**)&fl,  g_feat_l);
    cudaGetSymbolAddress((void**)&yph, g_ypi_h);
    cudaGetSymbolAddress((void**)&ypl, g_ypi_l);
    cudaGetSymbolAddress((void**)&yvh, g_yvf_h);
    cudaGetSymbolAddress((void**)&yvl, g_yvf_l);
    cudaGetSymbolAddress((void**)&z1ph, g_z1p_h);
    cudaGetSymbolAddress((void**)&z1pl, g_z1p_l);
    cudaGetSymbolAddress((void**)&z1vh, g_z1v_h);
    cudaGetSymbolAddress((void**)&z1vl, g_z1v_l);
    cudaGetSymbolAddress((void**)&wh,  g_w_h);
    cudaGetSymbolAddress((void**)&wlp, g_w_l);
    cudaGetSymbolAddress((void**)&hh,  g_hh);
    cudaGetSymbolAddress((void**)&hl,  g_hl);
    float* out = (float*)d_out;

    size_t tg_smem = (size_t)2 * STGB * sizeof(bf16);
    cudaFuncSetAttribute((const void*)tgemm, cudaFuncAttributeMaxDynamicSharedMemorySize, (int)tg_smem);
    cudaFuncSetAttribute((const void*)lstm_recur, cudaFuncAttributeMaxDynamicSharedMemorySize, LSTM_SMEM);

    // converts
    cvt_pair<<<2048, 256>>>(features, fh, fl, (size_t)NR * DD / 4);
    cvt3<<<512, 256>>>(Wihpi, wh + WOFF_IHPI, wlp + WOFF_IHPI, (size_t)G4 * DD / 4,
                       Wihvf, wh + WOFF_IHVF, wlp + WOFF_IHVF, (size_t)G4 * DD / 4,
                       polw1, wh + WOFF_PW1,  wlp + WOFF_PW1,  (size_t)HH * HH / 4);
    cvt3<<<256, 256>>>(polw2, wh + WOFF_PW2,  wlp + WOFF_PW2,  (size_t)HH * HH / 4,
                       valw1, wh + WOFF_VW1,  wlp + WOFF_VW1,  (size_t)HH * HH / 4,
                       valw2, wh + WOFF_VW2,  wlp + WOFF_VW2,  (size_t)HH * HH / 4);

    // input GEMMs
    tgemm<<<dim3(G4 / 128, NR / 128), 256, tg_smem>>>(fh, fl, wh + WOFF_IHPI, wlp + WOFF_IHPI,
                                                      bihpi, bhhpi, Gpi, nullptr, nullptr, G4, 0);
    tgemm<<<dim3(G4 / 128, NR / 128), 256, tg_smem>>>(fh, fl, wh + WOFF_IHVF, wlp + WOFF_IHVF,
                                                      bihvf, bhhvf, Gvf, nullptr, nullptr, G4, 0);

    // recurrence
    lstm_recur<<<128, 256, LSTM_SMEM>>>(Gpi, Gvf, starts, h0pi, c0pi, h0vf, c0vf,
                                        Whhpi, Whhvf, yph, ypl, yvh, yvl, hh, hl, out);

    // MLP layer 1 (bf16-split out, relu)
    tgemm<<<dim3(HH / 128, NR / 128), 256, tg_smem>>>(yph, ypl, wh + WOFF_PW1, wlp + WOFF_PW1,
                                                      polb1, nullptr, nullptr, z1ph, z1pl, HH, 1);
    tgemm<<<dim3(HH / 128, NR / 128), 256, tg_smem>>>(yvh, yvl, wh + WOFF_VW1, wlp + WOFF_VW1,
                                                      valb1, nullptr, nullptr, z1vh, z1vl, HH, 1);

    // MLP layer 2 (fp32 out)
    tgemm<<<dim3(HH / 128, NR / 128), 256, tg_smem>>>(z1ph, z1pl, wh + WOFF_PW2, wlp + WOFF_PW2,
                                                      polb2, nullptr, Z2pi, nullptr, nullptr, HH, 0);
    tgemm<<<dim3(HH / 128, NR / 128), 256, tg_smem>>>(z1vh, z1vl, wh + WOFF_VW2, wlp + WOFF_VW2,
                                                      valb2, nullptr, Z2vf, nullptr, nullptr, HH, 0);

    // heads
    head_kernel<<<NR, 128>>>(Z2pi, Z2vf, aw, ab, cw, cb, out);
}

// round 13
// speedup vs baseline: 1.1009x; 1.1009x over previous
#include <cuda_runtime.h>
#include <cuda_bf16.h>
#include <cuda_fp16.h>
#include <math.h>
#include <stdint.h>

// Problem constants
#define BB 128
#define TT 512
#define DD 512
#define HH 512
#define G4 2048
#define NR (BB*TT)
#define AA 32

typedef __nv_bfloat16 bf16;
typedef __half fp16;

// ---------------- scratch (device globals) ----------------
__device__ float g_Gpi[(size_t)NR * G4];
__device__ float g_Gvf[(size_t)NR * G4];
__device__ float g_Z2pi[(size_t)NR * HH];
__device__ float g_Z2vf[(size_t)NR * HH];
__device__ unsigned g_bar_count4[4];
__device__ unsigned g_bar_gen4[4];

// bf16 hi/lo pairs (GEMM path, unchanged)
__device__ __align__(16) bf16 g_feat_h[(size_t)NR * DD];
__device__ __align__(16) bf16 g_feat_l[(size_t)NR * DD];
__device__ __align__(16) bf16 g_ypi_h[(size_t)NR * HH];
__device__ __align__(16) bf16 g_ypi_l[(size_t)NR * HH];
__device__ __align__(16) bf16 g_yvf_h[(size_t)NR * HH];
__device__ __align__(16) bf16 g_yvf_l[(size_t)NR * HH];
__device__ __align__(16) bf16 g_z1p_h[(size_t)NR * HH];
__device__ __align__(16) bf16 g_z1p_l[(size_t)NR * HH];
__device__ __align__(16) bf16 g_z1v_h[(size_t)NR * HH];
__device__ __align__(16) bf16 g_z1v_l[(size_t)NR * HH];
// h ping-pong: [lstm][pingpong][128][512], single fp16 (pre-masked for the consuming step)
__device__ __align__(16) fp16 g_hf[2 * 2 * BB * HH];
// weights blob
#define WOFF_IHPI 0
#define WOFF_IHVF 1048576
#define WOFF_PW1  2097152
#define WOFF_PW2  2359296
#define WOFF_VW1  2621440
#define WOFF_VW2  2883584
#define WTOT      3145728
__device__ __align__(16) bf16 g_w_h[WTOT];
__device__ __align__(16) bf16 g_w_l[WTOT];

__device__ __forceinline__ float sigf(float x) {
    return __fdividef(1.0f, 1.0f + __expf(-x));
}
__device__ __forceinline__ float ftanh(float x) {
    float e = __expf(2.0f * x);
    return 1.0f - __fdividef(2.0f, e + 1.0f);
}

// ---------------- PTX helpers ----------------
#define CP16(d, s) asm volatile("cp.async.cg.shared.global [%0], [%1], 16;" :: "r"(d), "l"(s) : "memory")
#define CP_COMMIT() asm volatile("cp.async.commit_group;" ::: "memory")
#define CP_WAIT0()  asm volatile("cp.async.wait_group 0;" ::: "memory")
#define CP_WAIT1()  asm volatile("cp.async.wait_group 1;" ::: "memory")

__device__ __forceinline__ uint32_t smem_u32(const void* p) {
    uint32_t a;
    asm("{ .reg .u64 t; cvta.to.shared.u64 t, %1; cvt.u32.u64 %0, t; }" : "=r"(a) : "l"(p));
    return a;
}

#define MMA16816(c, a, b) \
    asm volatile("mma.sync.aligned.m16n8k16.row.col.f32.bf16.bf16.f32 " \
        "{%0,%1,%2,%3}, {%4,%5,%6,%7}, {%8,%9}, {%0,%1,%2,%3};" \
        : "+f"((c)[0]), "+f"((c)[1]), "+f"((c)[2]), "+f"((c)[3]) \
        : "r"((a)[0]), "r"((a)[1]), "r"((a)[2]), "r"((a)[3]), "r"((b)[0]), "r"((b)[1]))

#define MMAF16(c, a, b) \
    asm volatile("mma.sync.aligned.m16n8k16.row.col.f32.f16.f16.f32 " \
        "{%0,%1,%2,%3}, {%4,%5,%6,%7}, {%8,%9}, {%0,%1,%2,%3};" \
        : "+f"((c)[0]), "+f"((c)[1]), "+f"((c)[2]), "+f"((c)[3]) \
        : "r"((a)[0]), "r"((a)[1]), "r"((a)[2]), "r"((a)[3]), "r"((b)[0]), "r"((b)[1]))

#define LDSM4(r0, r1, r2, r3, addr) \
    asm volatile("ldmatrix.sync.aligned.m8n8.x4.shared.b16 {%0,%1,%2,%3}, [%4];" \
        : "=r"(r0), "=r"(r1), "=r"(r2), "=r"(r3) : "r"(addr))
#define LDSM2(r0, r1, addr) \
    asm volatile("ldmatrix.sync.aligned.m8n8.x2.shared.b16 {%0,%1}, [%2];" \
        : "=r"(r0), "=r"(r1) : "r"(addr))

// ---------------- fp32 -> bf16 hi/lo converters ----------------
__device__ __forceinline__ void cvt_one(const float* __restrict__ x,
                                        bf16* __restrict__ hi, bf16* __restrict__ lo, size_t i)
{
    float4 v = ((const float4*)x)[i];
    bf16 h0 = __float2bfloat16_rn(v.x), h1 = __float2bfloat16_rn(v.y);
    bf16 h2 = __float2bfloat16_rn(v.z), h3 = __float2bfloat16_rn(v.w);
    bf16 l0 = __float2bfloat16_rn(v.x - __bfloat162float(h0));
    bf16 l1 = __float2bfloat16_rn(v.y - __bfloat162float(h1));
    bf16 l2 = __float2bfloat16_rn(v.z - __bfloat162float(h2));
    bf16 l3 = __float2bfloat16_rn(v.w - __bfloat162float(h3));
    __nv_bfloat162 hp0; hp0.x = h0; hp0.y = h1;
    __nv_bfloat162 hp1; hp1.x = h2; hp1.y = h3;
    __nv_bfloat162 lp0; lp0.x = l0; lp0.y = l1;
    __nv_bfloat162 lp1; lp1.x = l2; lp1.y = l3;
    ((__nv_bfloat162*)hi)[2 * i]     = hp0;
    ((__nv_bfloat162*)hi)[2 * i + 1] = hp1;
    ((__nv_bfloat162*)lo)[2 * i]     = lp0;
    ((__nv_bfloat162*)lo)[2 * i + 1] = lp1;
}

__global__ __launch_bounds__(256) void cvt_pair(const float* __restrict__ x,
                                                bf16* __restrict__ hi, bf16* __restrict__ lo, size_t n4)
{
    for (size_t i = blockIdx.x * blockDim.x + threadIdx.x; i < n4; i += (size_t)gridDim.x * blockDim.x)
        cvt_one(x, hi, lo, i);
}

__global__ __launch_bounds__(256) void cvt3(
    const float* __restrict__ x0, bf16* __restrict__ h0, bf16* __restrict__ l0, size_t n0,
    const float* __restrict__ x1, bf16* __restrict__ h1, bf16* __restrict__ l1, size_t n1,
    const float* __restrict__ x2, bf16* __restrict__ h2, bf16* __restrict__ l2, size_t n2)
{
    size_t tot = n0 + n1 + n2;
    for (size_t i = blockIdx.x * blockDim.x + threadIdx.x; i < tot; i += (size_t)gridDim.x * blockDim.x) {
        if (i < n0) cvt_one(x0, h0, l0, i);
        else if (i < n0 + n1) cvt_one(x1, h1, l1, i - n0);
        else cvt_one(x2, h2, l2, i - n0 - n1);
    }
}

// ---------------- HMMA bf16-split GEMM (R10, unchanged) ----------------
#define KSTG 32
#define ROWP 40
#define MATB (128 * ROWP)
#define STGB (4 * MATB)
__global__ __launch_bounds__(256, 1) void tgemm(
    const bf16* __restrict__ Ah, const bf16* __restrict__ Al,
    const bf16* __restrict__ Wh, const bf16* __restrict__ Wl,
    const float* __restrict__ b1, const float* __restrict__ b2,
    float* __restrict__ C, bf16* __restrict__ Ch, bf16* __restrict__ Cl,
    int N, int relu)
{
    extern __shared__ bf16 smbf[];
    const int tid  = threadIdx.x;
    const int wid  = tid >> 5, lane = tid & 31;
    const int g    = lane >> 2, tig = lane & 3;
    const int m0   = (wid & 3) * 32;
    const int n0   = (wid >> 2) * 64;
    const size_t arow0 = (size_t)blockIdx.y * 128;
    const size_t brow0 = (size_t)blockIdx.x * 128;

    const int a_lrow = ((lane >> 3) & 1) * 8 + (lane & 7);
    const int a_kof  = (lane >> 4) * 8;
    const int b_lrow = lane & 7;
    const int b_kof  = ((lane >> 3) & 1) * 8;

    const int lmat = tid >> 6, t64 = tid & 63;
    const bf16* gsrc;
    if      (lmat == 0) gsrc = Ah + arow0 * 512;
    else if (lmat == 1) gsrc = Al + arow0 * 512;
    else if (lmat == 2) gsrc = Wh + brow0 * 512;
    else                gsrc = Wl + brow0 * 512;
    const uint32_t sbase = smem_u32(smbf);
    const uint32_t sdstm = sbase + (uint32_t)lmat * (MATB * 2);

    float acc[2][8][4];
#pragma unroll
    for (int i = 0; i < 2; i++)
#pragma unroll
        for (int j = 0; j < 8; j++)
#pragma unroll
            for (int q = 0; q < 4; q++) acc[i][j][q] = 0.0f;

#pragma unroll
    for (int s = 0; s < 2; s++) {
        const uint32_t db = sdstm + (uint32_t)s * (STGB * 2);
        const int k0 = s * KSTG;
#pragma unroll
        for (int i = 0; i < 8; i++) {
            int idx = i * 64 + t64;
            int row = idx >> 2, gg = idx & 3;
            CP16(db + (uint32_t)row * (ROWP * 2) + (uint32_t)gg * 16,
                 gsrc + (size_t)row * 512 + k0 + gg * 8);
        }
        CP_COMMIT();
    }

    const int NSTG = 512 / KSTG;
#pragma unroll 1
    for (int c = 0; c < NSTG; c++) {
        if (c < NSTG - 2) { CP_WAIT1(); } else { CP_WAIT0(); }
        __syncthreads();
        const uint32_t sS = sbase + (uint32_t)(c & 1) * (STGB * 2);
        const uint32_t sAh_u = sS;
        const uint32_t sAl_u = sS + MATB * 2;
        const uint32_t sWh_u = sS + 2 * MATB * 2;
        const uint32_t sWl_u = sS + 3 * MATB * 2;
#pragma unroll
        for (int kk = 0; kk < KSTG; kk += 16) {
            uint32_t ah[2][4], al[2][4];
#pragma unroll
            for (int tm = 0; tm < 2; tm++) {
                uint32_t aoff = (uint32_t)((m0 + tm * 16 + a_lrow) * ROWP + kk + a_kof) * 2;
                LDSM4(ah[tm][0], ah[tm][1], ah[tm][2], ah[tm][3], sAh_u + aoff);
                LDSM4(al[tm][0], al[tm][1], al[tm][2], al[tm][3], sAl_u + aoff);
            }
            uint32_t bh[8][2], bl[8][2];
#pragma unroll
            for (int tn = 0; tn < 8; tn++) {
                uint32_t boff = (uint32_t)((n0 + tn * 8 + b_lrow) * ROWP + kk + b_kof) * 2;
                LDSM2(bh[tn][0], bh[tn][1], sWh_u + boff);
                LDSM2(bl[tn][0], bl[tn][1], sWl_u + boff);
            }
#pragma unroll
            for (int tm = 0; tm < 2; tm++)
#pragma unroll
                for (int tn = 0; tn < 8; tn++) {
                    MMA16816(acc[tm][tn], ah[tm], bh[tn]);
                    MMA16816(acc[tm][tn], ah[tm], bl[tn]);
                    MMA16816(acc[tm][tn], al[tm], bh[tn]);
                }
        }
        __syncthreads();
        if (c + 2 < NSTG) {
            const uint32_t db = sdstm + (uint32_t)(c & 1) * (STGB * 2);
            const int k0 = (c + 2) * KSTG;
#pragma unroll
            for (int i = 0; i < 8; i++) {
                int idx = i * 64 + t64;
                int row = idx >> 2, gg = idx & 3;
                CP16(db + (uint32_t)row * (ROWP * 2) + (uint32_t)gg * 16,
                     gsrc + (size_t)row * 512 + k0 + gg * 8);
            }
            CP_COMMIT();
        }
    }

#pragma unroll
    for (int tn = 0; tn < 8; tn++) {
        int cc = (int)brow0 + n0 + tn * 8 + 2 * tig;
        float bv0 = b1[cc]     + (b2 ? b2[cc]     : 0.0f);
        float bv1 = b1[cc + 1] + (b2 ? b2[cc + 1] : 0.0f);
#pragma unroll
        for (int tm = 0; tm < 2; tm++) {
            size_t r0 = arow0 + m0 + tm * 16 + g;
            float v[4];
            v[0] = acc[tm][tn][0] + bv0;
            v[1] = acc[tm][tn][1] + bv1;
            v[2] = acc[tm][tn][2] + bv0;
            v[3] = acc[tm][tn][3] + bv1;
            if (relu) {
#pragma unroll
                for (int q = 0; q < 4; q++) v[q] = fmaxf(v[q], 0.f);
            }
            if (Ch) {
                __nv_bfloat162 h0, h1, l0, l1;
                h0.x = __float2bfloat16_rn(v[0]); h0.y = __float2bfloat16_rn(v[1]);
                h1.x = __float2bfloat16_rn(v[2]); h1.y = __float2bfloat16_rn(v[3]);
                l0.x = __float2bfloat16_rn(v[0] - __bfloat162float(h0.x));
                l0.y = __float2bfloat16_rn(v[1] - __bfloat162float(h0.y));
                l1.x = __float2bfloat16_rn(v[2] - __bfloat162float(h1.x));
                l1.y = __float2bfloat16_rn(v[3] - __bfloat162float(h1.y));
                *(__nv_bfloat162*)(Ch + r0 * (size_t)N + cc)       = h0;
                *(__nv_bfloat162*)(Cl + r0 * (size_t)N + cc)       = l0;
                *(__nv_bfloat162*)(Ch + (r0 + 8) * (size_t)N + cc) = h1;
                *(__nv_bfloat162*)(Cl + (r0 + 8) * (size_t)N + cc) = l1;
            } else {
                *(float2*)(C + r0 * (size_t)N + cc)       = make_float2(v[0], v[1]);
                *(float2*)(C + (r0 + 8) * (size_t)N + cc) = make_float2(v[2], v[3]);
            }
        }
    }
}

// ---------------- per-group software barrier (32 CTAs per group) ----------------
__device__ __forceinline__ void grid_bar_grp(int grp, int nct) {
    __threadfence();
    __syncthreads();
    if (threadIdx.x == 0) {
        volatile unsigned* vgen = &g_bar_gen4[grp];
        unsigned g = *vgen;
        unsigned a = atomicAdd(&g_bar_count4[grp], 1u);
        if (a == (unsigned)nct - 1u) {
            g_bar_count4[grp] = 0u;
            __threadfence();
            atomicAdd(&g_bar_gen4[grp], 1u);
        } else {
            while (*vgen == g) { }
        }
        __threadfence();
    }
    __syncthreads();
}

// ---------------- persistent recurrent kernel: fp16 2-pass ----------------
// h stored as single fp16 (pre-masked). W split: Wh=fp16(W), Wl=fp16((W-Wh)*2048).
// gates = h@Wh + (h@Wl)*2^-11. 8 MMAs per k16 (vs 12), staging traffic halved.
#define RPAD 72
#define WPAD 520
#define SGPAD 72
#define HBUF (64 * RPAD * 2)
#define OFF_WH   0
#define OFF_WL   (64 * WPAD * 2)
#define OFF_HB0  (2 * 64 * WPAD * 2)
#define OFF_HB1  (OFF_HB0 + HBUF)
#define OFF_SG   (OFF_HB0 + 2 * HBUF)
#define OFF_MASK (OFF_SG + 64 * SGPAD * 4)
#define OFF_SC   (OFF_MASK + 128 * 4)
#define LSTM_SMEM (OFF_SC + 64 * 16 * 4)
#define WLSCALE 4.8828125e-4f   // 2^-11

__global__ __launch_bounds__(256, 1) void lstm_recur(
    const float* __restrict__ Gpi, const float* __restrict__ Gvf,
    const float* __restrict__ starts,
    const float* __restrict__ h0pi, const float* __restrict__ c0pi,
    const float* __restrict__ h0vf, const float* __restrict__ c0vf,
    const float* __restrict__ Whhpi, const float* __restrict__ Whhvf,
    bf16* __restrict__ Yph, bf16* __restrict__ Ypl,
    bf16* __restrict__ Yvh, bf16* __restrict__ Yvl,
    fp16* __restrict__ hfg,
    float* __restrict__ out)
{
    extern __shared__ char sm8[];
    fp16*  sWh = (fp16*)(sm8 + OFF_WH);
    fp16*  sWl = (fp16*)(sm8 + OFF_WL);
    float* sg  = (float*)(sm8 + OFF_SG);
    float* smk = (float*)(sm8 + OFF_MASK);
    float* sc  = (float*)(sm8 + OFF_SC);

    const int ct   = blockIdx.x;
    const int lstm = ct >> 6;
    const int grp  = ct >> 5;
    const int b0   = ((ct >> 5) & 1) * 64;
    const int cid  = ct & 31;
    const int hc0  = cid * 16;
    const int tx   = threadIdx.x;
    const int wid  = tx >> 5, lane = tx & 31;
    const int g    = lane >> 2, tig = lane & 3;
    const int m0w  = (wid & 1) * 32;
    const int n0w  = (wid >> 1) * 16;

    const int a_lrow = ((lane >> 3) & 1) * 8 + (lane & 7);
    const int a_kof  = (lane >> 4) * 8;
    const int b_lrow = lane & 7;
    const int b_kof  = ((lane >> 3) & 1) * 8;

    const float* Gx  = lstm ? Gvf   : Gpi;
    const float* Whh = lstm ? Whhvf : Whhpi;
    const float* h0  = lstm ? h0vf  : h0pi;
    const float* c0  = lstm ? c0vf  : c0pi;
    bf16* Yh = lstm ? Yvh : Yph;
    bf16* Yl = lstm ? Yvl : Ypl;
    fp16* hfb = hfg + lstm * 2 * BB * HH;

    const uint32_t sb = smem_u32(sm8);
    const uint32_t shb[2] = { sb + OFF_HB0, sb + OFF_HB1 };
    const uint32_t sWh_u = sb + OFF_WH;
    const uint32_t sWl_u = sb + OFF_WL;

    // load + split Whh slice (fp16 hi + scaled lo)
    for (int s = 0; s < 128; s++) {
        int idx = tx + s * 256;
        int j = idx >> 9, k = idx & 511;
        int gc = ((j >> 4) << 9) + hc0 + (j & 15);
        float w = Whh[(size_t)gc * HH + k];
        fp16 hi = __float2half_rn(w);
        sWh[j * WPAD + k] = hi;
        sWl[j * WPAD + k] = __float2half_rn((w - __half2float(hi)) * 2048.0f);
    }
    // init c and h0 (ping 0, pre-masked, fp16)
    for (int s = 0; s < 4; s++) {
        int idx = tx + s * 256;
        int br = idx >> 4, q = idx & 15;
        int b = b0 + br;
        sc[br * 16 + q] = c0[b * HH + hc0 + q];
        float m0 = 1.0f - starts[b * TT];
        hfb[b * HH + hc0 + q] = __float2half_rn(h0[b * HH + hc0 + q] * m0);
    }
    grid_bar_grp(grp, 32);

    const int ebr = tx >> 2;
    const int ekb = (tx & 3) << 2;
    const int eb  = b0 + ebr;

    for (int t = 0; t < TT; t++) {
        const int cur = t & 1;
        const fp16* hcF = hfb + cur * BB * HH;

        // G prefetch for this step
        const size_t grow = ((size_t)eb * TT + t) * G4 + hc0 + ekb;
        const float4 pgi = *(const float4*)(Gx + grow);
        const float4 pgf = *(const float4*)(Gx + grow + 512);
        const float4 pgg = *(const float4*)(Gx + grow + 1024);
        const float4 pgo = *(const float4*)(Gx + grow + 1536);

        // prefetch h chunk 0 (K 0..63): 512 granules of 16B, 2 per thread
#pragma unroll
        for (int i = 0; i < 2; i++) {
            int idx = tx + i * 256;
            int row = idx >> 3, gg = idx & 7;
            uint32_t so = (uint32_t)row * (RPAD * 2) + (uint32_t)gg * 16;
            size_t  go = (size_t)(b0 + row) * 512 + gg * 8;
            CP16(shb[0] + so, hcF + go);
        }
        CP_COMMIT();

        // masks
        if (tx < 64) smk[tx] = 1.0f - starts[(b0 + tx) * TT + t];
        else if (tx < 128) {
            int br = tx - 64;
            smk[64 + br] = (t + 1 < TT) ? (1.0f - starts[(b0 + br) * TT + t + 1]) : 1.0f;
        }

        float acc[2][2][4], accB[2][2][4];
#pragma unroll
        for (int tm = 0; tm < 2; tm++)
#pragma unroll
            for (int tn = 0; tn < 2; tn++)
#pragma unroll
                for (int q = 0; q < 4; q++) { acc[tm][tn][q] = 0.0f; accB[tm][tn][q] = 0.0f; }

#pragma unroll 1
        for (int c = 0; c < 8; c++) {
            const int buf = c & 1;
            if (c < 7) {
                const int nb = buf ^ 1;
                const int kc = (c + 1) * 64;
#pragma unroll
                for (int i = 0; i < 2; i++) {
                    int idx = tx + i * 256;
                    int row = idx >> 3, gg = idx & 7;
                    uint32_t so = (uint32_t)row * (RPAD * 2) + (uint32_t)gg * 16;
                    size_t  go = (size_t)(b0 + row) * 512 + kc + gg * 8;
                    CP16(shb[nb] + so, hcF + go);
                }
                CP_COMMIT();
                CP_WAIT1();
            } else {
                CP_WAIT0();
            }
            __syncthreads();
            const uint32_t Sf_u = shb[buf];
#pragma unroll
            for (int k16 = 0; k16 < 64; k16 += 16) {
                uint32_t ah[2][4];
#pragma unroll
                for (int tm = 0; tm < 2; tm++) {
                    uint32_t aoff = (uint32_t)((m0w + tm * 16 + a_lrow) * RPAD + k16 + a_kof) * 2;
                    LDSM4(ah[tm][0], ah[tm][1], ah[tm][2], ah[tm][3], Sf_u + aoff);
                }
                const int kglob = c * 64 + k16 + b_kof;
                uint32_t bh[2][2], bl[2][2];
#pragma unroll
                for (int tn = 0; tn < 2; tn++) {
                    uint32_t boff = (uint32_t)((n0w + tn * 8 + b_lrow) * WPAD + kglob) * 2;
                    LDSM2(bh[tn][0], bh[tn][1], sWh_u + boff);
                    LDSM2(bl[tn][0], bl[tn][1], sWl_u + boff);
                }
#pragma unroll
                for (int tm = 0; tm < 2; tm++)
#pragma unroll
                    for (int tn = 0; tn < 2; tn++) {
                        MMAF16(acc[tm][tn],  ah[tm], bh[tn]);
                        MMAF16(accB[tm][tn], ah[tm], bl[tn]);
                    }
            }
            __syncthreads();
        }

        // publish gate preactivations: acc + accB*2^-11
#pragma unroll
        for (int tm = 0; tm < 2; tm++)
#pragma unroll
            for (int tn = 0; tn < 2; tn++) {
                int r = m0w + 16 * tm + g;
                int c0i = n0w + tn * 8 + 2 * tig;
                *(float2*)&sg[r * SGPAD + c0i] =
                    make_float2(acc[tm][tn][0] + accB[tm][tn][0] * WLSCALE,
                                acc[tm][tn][1] + accB[tm][tn][1] * WLSCALE);
                *(float2*)&sg[(r + 8) * SGPAD + c0i] =
                    make_float2(acc[tm][tn][2] + accB[tm][tn][2] * WLSCALE,
                                acc[tm][tn][3] + accB[tm][tn][3] * WLSCALE);
            }
        __syncthreads();

        // elementwise update
        {
            const float mcur = smk[ebr];
            const float mnxt = smk[64 + ebr];
            const float gi_[4] = {pgi.x, pgi.y, pgi.z, pgi.w};
            const float gf_[4] = {pgf.x, pgf.y, pgf.z, pgf.w};
            const float gg_[4] = {pgg.x, pgg.y, pgg.z, pgg.w};
            const float go_[4] = {pgo.x, pgo.y, pgo.z, pgo.w};
            float hn[4];
#pragma unroll
            for (int i = 0; i < 4; i++) {
                int q = ekb + i;
                float vi = sg[ebr * SGPAD + q]      + gi_[i];
                float vf = sg[ebr * SGPAD + 16 + q] + gf_[i];
                float vg = sg[ebr * SGPAD + 32 + q] + gg_[i];
                float vo = sg[ebr * SGPAD + 48 + q] + go_[i];
                float cc = sc[ebr * 16 + q] * mcur;
                float cn = sigf(vf) * cc + sigf(vi) * ftanh(vg);
                hn[i] = sigf(vo) * ftanh(cn);
                sc[ebr * 16 + q] = cn;
            }
            // Y (unmasked) bf16 split — MLP path keeps full accuracy
            {
                size_t yo = ((size_t)eb * TT + t) * HH + hc0 + ekb;
                __nv_bfloat162 h01, h23, l01, l23;
                h01.x = __float2bfloat16_rn(hn[0]); h01.y = __float2bfloat16_rn(hn[1]);
                h23.x = __float2bfloat16_rn(hn[2]); h23.y = __float2bfloat16_rn(hn[3]);
                l01.x = __float2bfloat16_rn(hn[0] - __bfloat162float(h01.x));
                l01.y = __float2bfloat16_rn(hn[1] - __bfloat162float(h01.y));
                l23.x = __float2bfloat16_rn(hn[2] - __bfloat162float(h23.x));
                l23.y = __float2bfloat16_rn(hn[3] - __bfloat162float(h23.y));
                *(__nv_bfloat162*)(Yh + yo)     = h01;
                *(__nv_bfloat162*)(Yh + yo + 2) = h23;
                *(__nv_bfloat162*)(Yl + yo)     = l01;
                *(__nv_bfloat162*)(Yl + yo + 2) = l23;
            }
            if (t + 1 < TT) {
                fp16* hnF = hfb + ((t + 1) & 1) * BB * HH;
                size_t ho = (size_t)eb * HH + hc0 + ekb;
                __half2 p01, p23;
                p01.x = __float2half_rn(hn[0] * mnxt); p01.y = __float2half_rn(hn[1] * mnxt);
                p23.x = __float2half_rn(hn[2] * mnxt); p23.y = __float2half_rn(hn[3] * mnxt);
                *(__half2*)(hnF + ho)     = p01;
                *(__half2*)(hnF + ho + 2) = p23;
            } else {
                float* oh = out + (size_t)3 * NR + (size_t)lstm * 2 * NR;
#pragma unroll
                for (int i = 0; i < 4; i++)
                    oh[eb * HH + hc0 + ekb + i] = hn[i];
            }
        }
        grid_bar_grp(grp, 32);
    }

    // final c -> out
    float* oc = out + (size_t)3 * NR + (size_t)lstm * 2 * NR + NR;
    for (int s = 0; s < 4; s++) {
        int idx = tx + s * 256;
        int br = idx >> 4, q = idx & 15;
        oc[(b0 + br) * HH + hc0 + q] = sc[br * 16 + q];
    }
}

// ---------------- heads ----------------
__global__ __launch_bounds__(128) void head_kernel(
    const float* __restrict__ Zpi, const float* __restrict__ Zvf,
    const float* __restrict__ aw, const float* __restrict__ ab,
    const float* __restrict__ cw, const float* __restrict__ cb,
    float* __restrict__ out)
{
    __shared__ float sx[512];
    __shared__ float slog[32];
    __shared__ float sval[4];
    const int n  = blockIdx.x;
    const int tx = threadIdx.x;

    ((float4*)sx)[tx] = ((const float4*)(Zpi + (size_t)n * 512))[tx];

    float4 xv = ((const float4*)(Zvf + (size_t)n * 512))[tx];
    float4 wv = ((const float4*)cw)[tx];
    float v = xv.x * wv.x + xv.y * wv.y + xv.z * wv.z + xv.w * wv.w;
#pragma unroll
    for (int off = 16; off; off >>= 1) v += __shfl_xor_sync(0xffffffffu, v, off);
    if ((tx & 31) == 0) sval[tx >> 5] = v;
    __syncthreads();

    const int l = tx >> 2;
    const int part = tx & 3;
    const float* wl = aw + l * 512 + part * 128;
    const float* xl = sx + part * 128;
    float s = 0.0f;
#pragma unroll 8
    for (int k4 = 0; k4 < 32; k4++) {
        float4 a = ((const float4*)xl)[k4];
        float4 w = ((const float4*)wl)[k4];
        s += a.x * w.x + a.y * w.y + a.z * w.z + a.w * w.w;
    }
    s += __shfl_xor_sync(0xffffffffu, s, 1);
    s += __shfl_xor_sync(0xffffffffu, s, 2);
    if (part == 0) slog[l] = s + ab[l];
    __syncthreads();

    if (tx < 32) {
        float lv = slog[tx];
        float m = lv; int mi = tx;
#pragma unroll
        for (int off = 16; off; off >>= 1) {
            float om = __shfl_xor_sync(0xffffffffu, m, off);
            int   oi = __shfl_xor_sync(0xffffffffu, mi, off);
            if (om > m || (om == m && oi < mi)) { m = om; mi = oi; }
        }
        float e = __expf(lv - m);
#pragma unroll
        for (int off = 16; off; off >>= 1) e += __shfl_xor_sync(0xffffffffu, e, off);
        if (tx == 0) {
            out[n] = (float)mi;
            out[(size_t)NR + n] = sval[0] + sval[1] + sval[2] + sval[3] + cb[0];
            out[(size_t)2 * NR + n] = -__logf(e);
        }
    }
}

// ---------------- launch ----------------
extern "C" void kernel_launch(void* const* d_in, const int* in_sizes, int n_in,
                              void* d_out, int out_size)
{
    const float* features = (const float*)d_in[0];
    const float* starts   = (const float*)d_in[1];
    const float* h0pi = (const float*)d_in[2];
    const float* c0pi = (const float*)d_in[3];
    const float* h0vf = (const float*)d_in[4];
    const float* c0vf = (const float*)d_in[5];
    const float* Wihpi = (const float*)d_in[6];
    const float* Whhpi = (const float*)d_in[7];
    const float* bihpi = (const float*)d_in[8];
    const float* bhhpi = (const float*)d_in[9];
    const float* Wihvf = (const float*)d_in[10];
    const float* Whhvf = (const float*)d_in[11];
    const float* bihvf = (const float*)d_in[12];
    const float* bhhvf = (const float*)d_in[13];
    const float* polw1 = (const float*)d_in[14];
    const float* polb1 = (const float*)d_in[15];
    const float* polw2 = (const float*)d_in[16];
    const float* polb2 = (const float*)d_in[17];
    const float* valw1 = (const float*)d_in[18];
    const float* valb1 = (const float*)d_in[19];
    const float* valw2 = (const float*)d_in[20];
    const float* valb2 = (const float*)d_in[21];
    const float* aw = (const float*)d_in[22];
    const float* ab = (const float*)d_in[23];
    const float* cw = (const float*)d_in[24];
    const float* cb = (const float*)d_in[25];

    float *Gpi, *Gvf, *Z2pi, *Z2vf;
    cudaGetSymbolAddress((void**)&Gpi,  g_Gpi);
    cudaGetSymbolAddress((void**)&Gvf,  g_Gvf);
    cudaGetSymbolAddress((void**)&Z2pi, g_Z2pi);
    cudaGetSymbolAddress((void**)&Z2vf, g_Z2vf);
    bf16 *fh, *fl, *yph, *ypl, *yvh, *yvl, *z1ph, *z1pl, *z1vh, *z1vl, *wh, *wlp;
    fp16 *hf;
    cudaGetSymbolAddress((void**)&fh,  g_feat_h);
    cudaGetSymbolAddress((void**)&fl,  g_feat_l);
    cudaGetSymbolAddress((void**)&yph, g_ypi_h);
    cudaGetSymbolAddress((void**)&ypl, g_ypi_l);
    cudaGetSymbolAddress((void**)&yvh, g_yvf_h);
    cudaGetSymbolAddress((void**)&yvl, g_yvf_l);
    cudaGetSymbolAddress((void**)&z1ph, g_z1p_h);
    cudaGetSymbolAddress((void**)&z1pl, g_z1p_l);
    cudaGetSymbolAddress((void**)&z1vh, g_z1v_h);
    cudaGetSymbolAddress((void**)&z1vl, g_z1v_l);
    cudaGetSymbolAddress((void**)&wh,  g_w_h);
    cudaGetSymbolAddress((void**)&wlp, g_w_l);
    cudaGetSymbolAddress((void**)&hf,  g_hf);
    float* out = (float*)d_out;

    size_t tg_smem = (size_t)2 * STGB * sizeof(bf16);
    cudaFuncSetAttribute((const void*)tgemm, cudaFuncAttributeMaxDynamicSharedMemorySize, (int)tg_smem);
    cudaFuncSetAttribute((const void*)lstm_recur, cudaFuncAttributeMaxDynamicSharedMemorySize, LSTM_SMEM);

    // converts
    cvt_pair<<<2048, 256>>>(features, fh, fl, (size_t)NR * DD / 4);
    cvt3<<<512, 256>>>(Wihpi, wh + WOFF_IHPI, wlp + WOFF_IHPI, (size_t)G4 * DD / 4,
                       Wihvf, wh + WOFF_IHVF, wlp + WOFF_IHVF, (size_t)G4 * DD / 4,
                       polw1, wh + WOFF_PW1,  wlp + WOFF_PW1,  (size_t)HH * HH / 4);
    cvt3<<<256, 256>>>(polw2, wh + WOFF_PW2,  wlp + WOFF_PW2,  (size_t)HH * HH / 4,
                       valw1, wh + WOFF_VW1,  wlp + WOFF_VW1,  (size_t)HH * HH / 4,
                       valw2, wh + WOFF_VW2,  wlp + WOFF_VW2,  (size_t)HH * HH / 4);

    // input GEMMs
    tgemm<<<dim3(G4 / 128, NR / 128), 256, tg_smem>>>(fh, fl, wh + WOFF_IHPI, wlp + WOFF_IHPI,
                                                      bihpi, bhhpi, Gpi, nullptr, nullptr, G4, 0);
    tgemm<<<dim3(G4 / 128, NR / 128), 256, tg_smem>>>(fh, fl, wh + WOFF_IHVF, wlp + WOFF_IHVF,
                                                      bihvf, bhhvf, Gvf, nullptr, nullptr, G4, 0);

    // recurrence (fp16 2-pass)
    lstm_recur<<<128, 256, LSTM_SMEM>>>(Gpi, Gvf, starts, h0pi, c0pi, h0vf, c0vf,
                                        Whhpi, Whhvf, yph, ypl, yvh, yvl, hf, out);

    // MLP layer 1 (bf16-split out, relu)
    tgemm<<<dim3(HH / 128, NR / 128), 256, tg_smem>>>(yph, ypl, wh + WOFF_PW1, wlp + WOFF_PW1,
                                                      polb1, nullptr, nullptr, z1ph, z1pl, HH, 1);
    tgemm<<<dim3(HH / 128, NR / 128), 256, tg_smem>>>(yvh, yvl, wh + WOFF_VW1, wlp + WOFF_VW1,
                                                      valb1, nullptr, nullptr, z1vh, z1vl, HH, 1);

    // MLP layer 2 (fp32 out)
    tgemm<<<dim3(HH / 128, NR / 128), 256, tg_smem>>>(z1ph, z1pl, wh + WOFF_PW2, wlp + WOFF_PW2,
                                                      polb2, nullptr, Z2pi, nullptr, nullptr, HH, 0);
    tgemm<<<dim3(HH / 128, NR / 128), 256, tg_smem>>>(z1vh, z1vl, wh + WOFF_VW2, wlp + WOFF_VW2,
                                                      valb2, nullptr, Z2vf, nullptr, nullptr, HH, 0);

    // heads
    head_kernel<<<NR, 128>>>(Z2pi, Z2vf, aw, ab, cw, cb, out);
}

// round 16
// speedup vs baseline: 1.2397x; 1.1261x over previous
#include <cuda_runtime.h>
#include <cuda_bf16.h>
#include <cuda_fp16.h>
#include <math.h>
#include <stdint.h>

// Problem constants
#define BB 128
#define TT 512
#define DD 512
#define HH 512
#define G4 2048
#define NR (BB*TT)
#define AA 32

typedef __nv_bfloat16 bf16;
typedef __half fp16;

// ---------------- scratch (device globals) ----------------
__device__ float g_Gpi[(size_t)NR * G4];                       // pi gates fp32 (precise)
__device__ __align__(16) fp16 g_Gvf16[(size_t)NR * G4];        // vf gates fp16
__device__ float g_Z2pi[(size_t)NR * HH];
__device__ float g_Z2vf[(size_t)NR * HH];
__device__ unsigned g_bar_count4[4];
__device__ unsigned g_bar_gen4[4];

// pi input GEMM (precise): bf16 pairs
__device__ __align__(16) bf16 g_feat_h[(size_t)NR * DD];
__device__ __align__(16) bf16 g_feat_l[(size_t)NR * DD];
__device__ __align__(16) bf16 g_wpi_h[(size_t)G4 * DD];
__device__ __align__(16) bf16 g_wpi_l[(size_t)G4 * DD];
// vf input GEMM (fast): fp16 singles
__device__ __align__(16) fp16 g_feat16[(size_t)NR * DD];
__device__ __align__(16) fp16 g_wvf16[(size_t)G4 * DD];
// pi MLP path (precise): bf16 pairs
__device__ __align__(16) bf16 g_ypi_h[(size_t)NR * HH];
__device__ __align__(16) bf16 g_ypi_l[(size_t)NR * HH];
__device__ __align__(16) bf16 g_z1p_h[(size_t)NR * HH];
__device__ __align__(16) bf16 g_z1p_l[(size_t)NR * HH];
// vf MLP path (fast): fp16 singles
__device__ __align__(16) fp16 g_yvf16[(size_t)NR * HH];
__device__ __align__(16) fp16 g_z1v16[(size_t)NR * HH];
// h ping-pong: single fp16 (pre-masked) — both LSTMs (R12 proven)
__device__ __align__(16) fp16 g_hf[2 * 2 * BB * HH];
// pol weights bf16 pairs; val weights fp16 singles
#define WOFF_PW1  0
#define WOFF_PW2  262144
#define WPTOT     524288
__device__ __align__(16) bf16 g_w_h[WPTOT];
__device__ __align__(16) bf16 g_w_l[WPTOT];
#define WOFF_VW1  0
#define WOFF_VW2  262144
__device__ __align__(16) fp16 g_wval16[524288];

__device__ __forceinline__ float sigf(float x) {
    return __fdividef(1.0f, 1.0f + __expf(-x));
}
__device__ __forceinline__ float ftanh(float x) {
    float e = __expf(2.0f * x);
    return 1.0f - __fdividef(2.0f, e + 1.0f);
}

// ---------------- PTX helpers ----------------
#define CP16(d, s) asm volatile("cp.async.cg.shared.global [%0], [%1], 16;" :: "r"(d), "l"(s) : "memory")
#define CP_COMMIT() asm volatile("cp.async.commit_group;" ::: "memory")
#define CP_WAIT0()  asm volatile("cp.async.wait_group 0;" ::: "memory")
#define CP_WAIT1()  asm volatile("cp.async.wait_group 1;" ::: "memory")

__device__ __forceinline__ uint32_t smem_u32(const void* p) {
    uint32_t a;
    asm("{ .reg .u64 t; cvta.to.shared.u64 t, %1; cvt.u32.u64 %0, t; }" : "=r"(a) : "l"(p));
    return a;
}

#define MMA16816(c, a, b) \
    asm volatile("mma.sync.aligned.m16n8k16.row.col.f32.bf16.bf16.f32 " \
        "{%0,%1,%2,%3}, {%4,%5,%6,%7}, {%8,%9}, {%0,%1,%2,%3};" \
        : "+f"((c)[0]), "+f"((c)[1]), "+f"((c)[2]), "+f"((c)[3]) \
        : "r"((a)[0]), "r"((a)[1]), "r"((a)[2]), "r"((a)[3]), "r"((b)[0]), "r"((b)[1]))

#define MMAF16(c, a, b) \
    asm volatile("mma.sync.aligned.m16n8k16.row.col.f32.f16.f16.f32 " \
        "{%0,%1,%2,%3}, {%4,%5,%6,%7}, {%8,%9}, {%0,%1,%2,%3};" \
        : "+f"((c)[0]), "+f"((c)[1]), "+f"((c)[2]), "+f"((c)[3]) \
        : "r"((a)[0]), "r"((a)[1]), "r"((a)[2]), "r"((a)[3]), "r"((b)[0]), "r"((b)[1]))

#define LDSM4(r0, r1, r2, r3, addr) \
    asm volatile("ldmatrix.sync.aligned.m8n8.x4.shared.b16 {%0,%1,%2,%3}, [%4];" \
        : "=r"(r0), "=r"(r1), "=r"(r2), "=r"(r3) : "r"(addr))
#define LDSM2(r0, r1, addr) \
    asm volatile("ldmatrix.sync.aligned.m8n8.x2.shared.b16 {%0,%1}, [%2];" \
        : "=r"(r0), "=r"(r1) : "r"(addr))

#define WLSCALE 4.8828125e-4f   // 2^-11

// ---------------- converters ----------------
__device__ __forceinline__ void cvt_one(const float* __restrict__ x,
                                        bf16* __restrict__ hi, bf16* __restrict__ lo, size_t i)
{
    float4 v = ((const float4*)x)[i];
    bf16 h0 = __float2bfloat16_rn(v.x), h1 = __float2bfloat16_rn(v.y);
    bf16 h2 = __float2bfloat16_rn(v.z), h3 = __float2bfloat16_rn(v.w);
    bf16 l0 = __float2bfloat16_rn(v.x - __bfloat162float(h0));
    bf16 l1 = __float2bfloat16_rn(v.y - __bfloat162float(h1));
    bf16 l2 = __float2bfloat16_rn(v.z - __bfloat162float(h2));
    bf16 l3 = __float2bfloat16_rn(v.w - __bfloat162float(h3));
    __nv_bfloat162 hp0; hp0.x = h0; hp0.y = h1;
    __nv_bfloat162 hp1; hp1.x = h2; hp1.y = h3;
    __nv_bfloat162 lp0; lp0.x = l0; lp0.y = l1;
    __nv_bfloat162 lp1; lp1.x = l2; lp1.y = l3;
    ((__nv_bfloat162*)hi)[2 * i]     = hp0;
    ((__nv_bfloat162*)hi)[2 * i + 1] = hp1;
    ((__nv_bfloat162*)lo)[2 * i]     = lp0;
    ((__nv_bfloat162*)lo)[2 * i + 1] = lp1;
}
__device__ __forceinline__ void cvt_one_h(const float* __restrict__ x,
                                          fp16* __restrict__ y, size_t i)
{
    float4 v = ((const float4*)x)[i];
    __half2 a, b;
    a.x = __float2half_rn(v.x); a.y = __float2half_rn(v.y);
    b.x = __float2half_rn(v.z); b.y = __float2half_rn(v.w);
    ((__half2*)y)[2 * i]     = a;
    ((__half2*)y)[2 * i + 1] = b;
}

// 4 bf16-pair conversions in one launch
__global__ __launch_bounds__(256) void cvt4(
    const float* __restrict__ x0, bf16* __restrict__ h0, bf16* __restrict__ l0, size_t n0,
    const float* __restrict__ x1, bf16* __restrict__ h1, bf16* __restrict__ l1, size_t n1,
    const float* __restrict__ x2, bf16* __restrict__ h2, bf16* __restrict__ l2, size_t n2,
    const float* __restrict__ x3, bf16* __restrict__ h3, bf16* __restrict__ l3, size_t n3)
{
    size_t tot = n0 + n1 + n2 + n3;
    for (size_t i = blockIdx.x * blockDim.x + threadIdx.x; i < tot; i += (size_t)gridDim.x * blockDim.x) {
        if (i < n0) cvt_one(x0, h0, l0, i);
        else if (i < n0 + n1) cvt_one(x1, h1, l1, i - n0);
        else if (i < n0 + n1 + n2) cvt_one(x2, h2, l2, i - n0 - n1);
        else cvt_one(x3, h3, l3, i - n0 - n1 - n2);
    }
}

// 4 fp16-single conversions in one launch
__global__ __launch_bounds__(256) void cvt4h(
    const float* __restrict__ x0, fp16* __restrict__ y0, size_t n0,
    const float* __restrict__ x1, fp16* __restrict__ y1, size_t n1,
    const float* __restrict__ x2, fp16* __restrict__ y2, size_t n2,
    const float* __restrict__ x3, fp16* __restrict__ y3, size_t n3)
{
    size_t tot = n0 + n1 + n2 + n3;
    for (size_t i = blockIdx.x * blockDim.x + threadIdx.x; i < tot; i += (size_t)gridDim.x * blockDim.x) {
        if (i < n0) cvt_one_h(x0, y0, i);
        else if (i < n0 + n1) cvt_one_h(x1, y1, i - n0);
        else if (i < n0 + n1 + n2) cvt_one_h(x2, y2, i - n0 - n1);
        else cvt_one_h(x3, y3, i - n0 - n1 - n2);
    }
}

// ---------------- HMMA bf16-split GEMM (R12 proven; pi path) ----------------
#define KSTG 32
#define ROWP 40
#define MATB (128 * ROWP)
#define STGB (4 * MATB)
__global__ __launch_bounds__(256, 1) void tgemm(
    const bf16* __restrict__ Ah, const bf16* __restrict__ Al,
    const bf16* __restrict__ Wh, const bf16* __restrict__ Wl,
    const float* __restrict__ b1, const float* __restrict__ b2,
    float* __restrict__ C, bf16* __restrict__ Ch, bf16* __restrict__ Cl,
    int N, int relu)
{
    extern __shared__ bf16 smbf[];
    const int tid  = threadIdx.x;
    const int wid  = tid >> 5, lane = tid & 31;
    const int g    = lane >> 2, tig = lane & 3;
    const int m0   = (wid & 3) * 32;
    const int n0   = (wid >> 2) * 64;
    const size_t arow0 = (size_t)blockIdx.y * 128;
    const size_t brow0 = (size_t)blockIdx.x * 128;

    const int a_lrow = ((lane >> 3) & 1) * 8 + (lane & 7);
    const int a_kof  = (lane >> 4) * 8;
    const int b_lrow = lane & 7;
    const int b_kof  = ((lane >> 3) & 1) * 8;

    const int lmat = tid >> 6, t64 = tid & 63;
    const bf16* gsrc;
    if      (lmat == 0) gsrc = Ah + arow0 * 512;
    else if (lmat == 1) gsrc = Al + arow0 * 512;
    else if (lmat == 2) gsrc = Wh + brow0 * 512;
    else                gsrc = Wl + brow0 * 512;
    const uint32_t sbase = smem_u32(smbf);
    const uint32_t sdstm = sbase + (uint32_t)lmat * (MATB * 2);

    float acc[2][8][4];
#pragma unroll
    for (int i = 0; i < 2; i++)
#pragma unroll
        for (int j = 0; j < 8; j++)
#pragma unroll
            for (int q = 0; q < 4; q++) acc[i][j][q] = 0.0f;

#pragma unroll
    for (int s = 0; s < 2; s++) {
        const uint32_t db = sdstm + (uint32_t)s * (STGB * 2);
        const int k0 = s * KSTG;
#pragma unroll
        for (int i = 0; i < 8; i++) {
            int idx = i * 64 + t64;
            int row = idx >> 2, gg = idx & 3;
            CP16(db + (uint32_t)row * (ROWP * 2) + (uint32_t)gg * 16,
                 gsrc + (size_t)row * 512 + k0 + gg * 8);
        }
        CP_COMMIT();
    }

    const int NSTG = 512 / KSTG;
#pragma unroll 1
    for (int c = 0; c < NSTG; c++) {
        if (c < NSTG - 2) { CP_WAIT1(); } else { CP_WAIT0(); }
        __syncthreads();
        const uint32_t sS = sbase + (uint32_t)(c & 1) * (STGB * 2);
        const uint32_t sAh_u = sS;
        const uint32_t sAl_u = sS + MATB * 2;
        const uint32_t sWh_u = sS + 2 * MATB * 2;
        const uint32_t sWl_u = sS + 3 * MATB * 2;
#pragma unroll
        for (int kk = 0; kk < KSTG; kk += 16) {
            uint32_t ah[2][4], al[2][4];
#pragma unroll
            for (int tm = 0; tm < 2; tm++) {
                uint32_t aoff = (uint32_t)((m0 + tm * 16 + a_lrow) * ROWP + kk + a_kof) * 2;
                LDSM4(ah[tm][0], ah[tm][1], ah[tm][2], ah[tm][3], sAh_u + aoff);
                LDSM4(al[tm][0], al[tm][1], al[tm][2], al[tm][3], sAl_u + aoff);
            }
            uint32_t bh[8][2], bl[8][2];
#pragma unroll
            for (int tn = 0; tn < 8; tn++) {
                uint32_t boff = (uint32_t)((n0 + tn * 8 + b_lrow) * ROWP + kk + b_kof) * 2;
                LDSM2(bh[tn][0], bh[tn][1], sWh_u + boff);
                LDSM2(bl[tn][0], bl[tn][1], sWl_u + boff);
            }
#pragma unroll
            for (int tm = 0; tm < 2; tm++)
#pragma unroll
                for (int tn = 0; tn < 8; tn++) {
                    MMA16816(acc[tm][tn], ah[tm], bh[tn]);
                    MMA16816(acc[tm][tn], ah[tm], bl[tn]);
                    MMA16816(acc[tm][tn], al[tm], bh[tn]);
                }
        }
        __syncthreads();
        if (c + 2 < NSTG) {
            const uint32_t db = sdstm + (uint32_t)(c & 1) * (STGB * 2);
            const int k0 = (c + 2) * KSTG;
#pragma unroll
            for (int i = 0; i < 8; i++) {
                int idx = i * 64 + t64;
                int row = idx >> 2, gg = idx & 3;
                CP16(db + (uint32_t)row * (ROWP * 2) + (uint32_t)gg * 16,
                     gsrc + (size_t)row * 512 + k0 + gg * 8);
            }
            CP_COMMIT();
        }
    }

#pragma unroll
    for (int tn = 0; tn < 8; tn++) {
        int cc = (int)brow0 + n0 + tn * 8 + 2 * tig;
        float bv0 = b1[cc]     + (b2 ? b2[cc]     : 0.0f);
        float bv1 = b1[cc + 1] + (b2 ? b2[cc + 1] : 0.0f);
#pragma unroll
        for (int tm = 0; tm < 2; tm++) {
            size_t r0 = arow0 + m0 + tm * 16 + g;
            float v[4];
            v[0] = acc[tm][tn][0] + bv0;
            v[1] = acc[tm][tn][1] + bv1;
            v[2] = acc[tm][tn][2] + bv0;
            v[3] = acc[tm][tn][3] + bv1;
            if (relu) {
#pragma unroll
                for (int q = 0; q < 4; q++) v[q] = fmaxf(v[q], 0.f);
            }
            if (Ch) {
                __nv_bfloat162 h0, h1, l0, l1;
                h0.x = __float2bfloat16_rn(v[0]); h0.y = __float2bfloat16_rn(v[1]);
                h1.x = __float2bfloat16_rn(v[2]); h1.y = __float2bfloat16_rn(v[3]);
                l0.x = __float2bfloat16_rn(v[0] - __bfloat162float(h0.x));
                l0.y = __float2bfloat16_rn(v[1] - __bfloat162float(h0.y));
                l1.x = __float2bfloat16_rn(v[2] - __bfloat162float(h1.x));
                l1.y = __float2bfloat16_rn(v[3] - __bfloat162float(h1.y));
                *(__nv_bfloat162*)(Ch + r0 * (size_t)N + cc)       = h0;
                *(__nv_bfloat162*)(Cl + r0 * (size_t)N + cc)       = l0;
                *(__nv_bfloat162*)(Ch + (r0 + 8) * (size_t)N + cc) = h1;
                *(__nv_bfloat162*)(Cl + (r0 + 8) * (size_t)N + cc) = l1;
            } else {
                *(float2*)(C + r0 * (size_t)N + cc)       = make_float2(v[0], v[1]);
                *(float2*)(C + (r0 + 8) * (size_t)N + cc) = make_float2(v[2], v[3]);
            }
        }
    }
}

// ---------------- single-pass fp16 GEMM (vf path) ----------------
// C = A@W^T + b1 (+b2), A/W fp16, fp32 accum. Out: fp16 (Cf16, opt relu) or fp32 (Cf32).
__global__ __launch_bounds__(256, 1) void tgemm16s(
    const fp16* __restrict__ A, const fp16* __restrict__ W,
    const float* __restrict__ b1, const float* __restrict__ b2,
    fp16* __restrict__ Cf16, float* __restrict__ Cf32,
    int N, int relu)
{
    extern __shared__ fp16 smh[];
    const int tid  = threadIdx.x;
    const int wid  = tid >> 5, lane = tid & 31;
    const int g    = lane >> 2, tig = lane & 3;
    const int m0   = (wid & 3) * 32;
    const int n0   = (wid >> 2) * 64;
    const size_t arow0 = (size_t)blockIdx.y * 128;
    const size_t brow0 = (size_t)blockIdx.x * 128;

    const int a_lrow = ((lane >> 3) & 1) * 8 + (lane & 7);
    const int a_kof  = (lane >> 4) * 8;
    const int b_lrow = lane & 7;
    const int b_kof  = ((lane >> 3) & 1) * 8;

    const uint32_t sbase = smem_u32(smh);
    const fp16* Ab = A + arow0 * 512;
    const fp16* Wb = W + brow0 * 512;

    float acc[2][8][4];
#pragma unroll
    for (int i = 0; i < 2; i++)
#pragma unroll
        for (int j = 0; j < 8; j++)
#pragma unroll
            for (int q = 0; q < 4; q++) acc[i][j][q] = 0.0f;

#pragma unroll
    for (int s = 0; s < 2; s++) {
        const uint32_t db = sbase + (uint32_t)s * (2 * MATB * 2);
        const int k0 = s * KSTG;
#pragma unroll
        for (int i = 0; i < 4; i++) {
            int idx = tid + i * 256;
            int mat = idx >> 9, g512 = idx & 511;
            int row = g512 >> 2, gg = g512 & 3;
            const fp16* src = (mat ? Wb : Ab) + (size_t)row * 512 + k0 + gg * 8;
            CP16(db + (uint32_t)mat * (MATB * 2) + (uint32_t)row * (ROWP * 2) + (uint32_t)gg * 16, src);
        }
        CP_COMMIT();
    }

    const int NSTG = 512 / KSTG;
#pragma unroll 1
    for (int c = 0; c < NSTG; c++) {
        if (c < NSTG - 2) { CP_WAIT1(); } else { CP_WAIT0(); }
        __syncthreads();
        const uint32_t sS = sbase + (uint32_t)(c & 1) * (2 * MATB * 2);
        const uint32_t sA_u = sS;
        const uint32_t sW_u = sS + MATB * 2;
#pragma unroll
        for (int kk = 0; kk < KSTG; kk += 16) {
            uint32_t ah[2][4];
#pragma unroll
            for (int tm = 0; tm < 2; tm++) {
                uint32_t aoff = (uint32_t)((m0 + tm * 16 + a_lrow) * ROWP + kk + a_kof) * 2;
                LDSM4(ah[tm][0], ah[tm][1], ah[tm][2], ah[tm][3], sA_u + aoff);
            }
            uint32_t bh[8][2];
#pragma unroll
            for (int tn = 0; tn < 8; tn++) {
                uint32_t boff = (uint32_t)((n0 + tn * 8 + b_lrow) * ROWP + kk + b_kof) * 2;
                LDSM2(bh[tn][0], bh[tn][1], sW_u + boff);
            }
#pragma unroll
            for (int tm = 0; tm < 2; tm++)
#pragma unroll
                for (int tn = 0; tn < 8; tn++)
                    MMAF16(acc[tm][tn], ah[tm], bh[tn]);
        }
        __syncthreads();
        if (c + 2 < NSTG) {
            const uint32_t db = sbase + (uint32_t)(c & 1) * (2 * MATB * 2);
            const int k0 = (c + 2) * KSTG;
#pragma unroll
            for (int i = 0; i < 4; i++) {
                int idx = tid + i * 256;
                int mat = idx >> 9, g512 = idx & 511;
                int row = g512 >> 2, gg = g512 & 3;
                const fp16* src = (mat ? Wb : Ab) + (size_t)row * 512 + k0 + gg * 8;
                CP16(db + (uint32_t)mat * (MATB * 2) + (uint32_t)row * (ROWP * 2) + (uint32_t)gg * 16, src);
            }
            CP_COMMIT();
        }
    }

#pragma unroll
    for (int tn = 0; tn < 8; tn++) {
        int cc = (int)brow0 + n0 + tn * 8 + 2 * tig;
        float bv0 = b1[cc]     + (b2 ? b2[cc]     : 0.0f);
        float bv1 = b1[cc + 1] + (b2 ? b2[cc + 1] : 0.0f);
#pragma unroll
        for (int tm = 0; tm < 2; tm++) {
            size_t r0 = arow0 + m0 + tm * 16 + g;
            float v[4];
            v[0] = acc[tm][tn][0] + bv0;
            v[1] = acc[tm][tn][1] + bv1;
            v[2] = acc[tm][tn][2] + bv0;
            v[3] = acc[tm][tn][3] + bv1;
            if (relu) {
#pragma unroll
                for (int q = 0; q < 4; q++) v[q] = fmaxf(v[q], 0.f);
            }
            if (Cf16) {
                __half2 v01, v23;
                v01.x = __float2half_rn(v[0]); v01.y = __float2half_rn(v[1]);
                v23.x = __float2half_rn(v[2]); v23.y = __float2half_rn(v[3]);
                *(__half2*)(Cf16 + r0 * (size_t)N + cc)       = v01;
                *(__half2*)(Cf16 + (r0 + 8) * (size_t)N + cc) = v23;
            } else {
                *(float2*)(Cf32 + r0 * (size_t)N + cc)       = make_float2(v[0], v[1]);
                *(float2*)(Cf32 + (r0 + 8) * (size_t)N + cc) = make_float2(v[2], v[3]);
            }
        }
    }
}

// ---------------- per-group software barrier ----------------
__device__ __forceinline__ void grid_bar_grp(int grp, int nct) {
    __threadfence();
    __syncthreads();
    if (threadIdx.x == 0) {
        volatile unsigned* vgen = &g_bar_gen4[grp];
        unsigned g = *vgen;
        unsigned a = atomicAdd(&g_bar_count4[grp], 1u);
        if (a == (unsigned)nct - 1u) {
            g_bar_count4[grp] = 0u;
            __threadfence();
            atomicAdd(&g_bar_gen4[grp], 1u);
        } else {
            while (*vgen == g) { }
        }
        __threadfence();
    }
    __syncthreads();
}

// ---------------- persistent recurrent kernel: fp16 2-pass (R12 proven) ----------------
// pi: G fp32 in, Y bf16-pair out.  vf: G fp16 in, Y fp16 out.
#define RPAD 72
#define WPAD 520
#define SGPAD 72
#define HBUF (64 * RPAD * 2)
#define OFF_WH   0
#define OFF_WL   (64 * WPAD * 2)
#define OFF_HB0  (2 * 64 * WPAD * 2)
#define OFF_HB1  (OFF_HB0 + HBUF)
#define OFF_SG   (OFF_HB0 + 2 * HBUF)
#define OFF_MASK (OFF_SG + 64 * SGPAD * 4)
#define OFF_SC   (OFF_MASK + 128 * 4)
#define LSTM_SMEM (OFF_SC + 64 * 16 * 4)

__global__ __launch_bounds__(256, 1) void lstm_recur(
    const float* __restrict__ Gpi, const fp16* __restrict__ Gvf,
    const float* __restrict__ starts,
    const float* __restrict__ h0pi, const float* __restrict__ c0pi,
    const float* __restrict__ h0vf, const float* __restrict__ c0vf,
    const float* __restrict__ Whhpi, const float* __restrict__ Whhvf,
    bf16* __restrict__ Yph, bf16* __restrict__ Ypl,
    fp16* __restrict__ Yv16,
    fp16* __restrict__ hfg,
    float* __restrict__ out)
{
    extern __shared__ char sm8[];
    fp16*  sWh = (fp16*)(sm8 + OFF_WH);
    fp16*  sWl = (fp16*)(sm8 + OFF_WL);
    float* sg  = (float*)(sm8 + OFF_SG);
    float* smk = (float*)(sm8 + OFF_MASK);
    float* sc  = (float*)(sm8 + OFF_SC);

    const int ct   = blockIdx.x;
    const int lstm = ct >> 6;
    const int grp  = ct >> 5;
    const int b0   = ((ct >> 5) & 1) * 64;
    const int cid  = ct & 31;
    const int hc0  = cid * 16;
    const int tx   = threadIdx.x;
    const int wid  = tx >> 5, lane = tx & 31;
    const int g    = lane >> 2, tig = lane & 3;
    const int m0w  = (wid & 1) * 32;
    const int n0w  = (wid >> 1) * 16;

    const int a_lrow = ((lane >> 3) & 1) * 8 + (lane & 7);
    const int a_kof  = (lane >> 4) * 8;
    const int b_lrow = lane & 7;
    const int b_kof  = ((lane >> 3) & 1) * 8;

    const float* Whh = lstm ? Whhvf : Whhpi;
    const float* h0  = lstm ? h0vf  : h0pi;
    const float* c0  = lstm ? c0vf  : c0pi;
    fp16* hfb = hfg + lstm * 2 * BB * HH;

    const uint32_t sb = smem_u32(sm8);
    const uint32_t shb[2] = { sb + OFF_HB0, sb + OFF_HB1 };
    const uint32_t sWh_u = sb + OFF_WH;
    const uint32_t sWl_u = sb + OFF_WL;

    // load + split Whh slice (fp16 hi + scaled lo)
    for (int s = 0; s < 128; s++) {
        int idx = tx + s * 256;
        int j = idx >> 9, k = idx & 511;
        int gc = ((j >> 4) << 9) + hc0 + (j & 15);
        float w = Whh[(size_t)gc * HH + k];
        fp16 hi = __float2half_rn(w);
        sWh[j * WPAD + k] = hi;
        sWl[j * WPAD + k] = __float2half_rn((w - __half2float(hi)) * 2048.0f);
    }
    // init c and h0 (ping 0, pre-masked, fp16)
    for (int s = 0; s < 4; s++) {
        int idx = tx + s * 256;
        int br = idx >> 4, q = idx & 15;
        int b = b0 + br;
        sc[br * 16 + q] = c0[b * HH + hc0 + q];
        float m0 = 1.0f - starts[b * TT];
        hfb[b * HH + hc0 + q] = __float2half_rn(h0[b * HH + hc0 + q] * m0);
    }
    grid_bar_grp(grp, 32);

    const int ebr = tx >> 2;
    const int ekb = (tx & 3) << 2;
    const int eb  = b0 + ebr;

    for (int t = 0; t < TT; t++) {
        const int cur = t & 1;
        const fp16* hcF = hfb + cur * BB * HH;

        // G prefetch for this step (pi: fp32; vf: fp16)
        const size_t grow = ((size_t)eb * TT + t) * G4 + hc0 + ekb;
        float gi_[4], gf_[4], gg_[4], go_[4];
        if (lstm == 0) {
            const float4 a = *(const float4*)(Gpi + grow);
            const float4 b = *(const float4*)(Gpi + grow + 512);
            const float4 c = *(const float4*)(Gpi + grow + 1024);
            const float4 d = *(const float4*)(Gpi + grow + 1536);
            gi_[0]=a.x; gi_[1]=a.y; gi_[2]=a.z; gi_[3]=a.w;
            gf_[0]=b.x; gf_[1]=b.y; gf_[2]=b.z; gf_[3]=b.w;
            gg_[0]=c.x; gg_[1]=c.y; gg_[2]=c.z; gg_[3]=c.w;
            go_[0]=d.x; go_[1]=d.y; go_[2]=d.z; go_[3]=d.w;
        } else {
            __half2 a0 = *(const __half2*)(Gvf + grow),        a1 = *(const __half2*)(Gvf + grow + 2);
            __half2 b0h = *(const __half2*)(Gvf + grow + 512),  b1h = *(const __half2*)(Gvf + grow + 514);
            __half2 c0h = *(const __half2*)(Gvf + grow + 1024), c1h = *(const __half2*)(Gvf + grow + 1026);
            __half2 d0 = *(const __half2*)(Gvf + grow + 1536), d1 = *(const __half2*)(Gvf + grow + 1538);
            gi_[0]=__half2float(a0.x); gi_[1]=__half2float(a0.y); gi_[2]=__half2float(a1.x); gi_[3]=__half2float(a1.y);
            gf_[0]=__half2float(b0h.x); gf_[1]=__half2float(b0h.y); gf_[2]=__half2float(b1h.x); gf_[3]=__half2float(b1h.y);
            gg_[0]=__half2float(c0h.x); gg_[1]=__half2float(c0h.y); gg_[2]=__half2float(c1h.x); gg_[3]=__half2float(c1h.y);
            go_[0]=__half2float(d0.x); go_[1]=__half2float(d0.y); go_[2]=__half2float(d1.x); go_[3]=__half2float(d1.y);
        }

        // prefetch h chunk 0 (K 0..63): 512 granules of 16B, 2 per thread
#pragma unroll
        for (int i = 0; i < 2; i++) {
            int idx = tx + i * 256;
            int row = idx >> 3, gg = idx & 7;
            uint32_t so = (uint32_t)row * (RPAD * 2) + (uint32_t)gg * 16;
            size_t  go = (size_t)(b0 + row) * 512 + gg * 8;
            CP16(shb[0] + so, hcF + go);
        }
        CP_COMMIT();

        // masks
        if (tx < 64) smk[tx] = 1.0f - starts[(b0 + tx) * TT + t];
        else if (tx < 128) {
            int br = tx - 64;
            smk[64 + br] = (t + 1 < TT) ? (1.0f - starts[(b0 + br) * TT + t + 1]) : 1.0f;
        }

        float acc[2][2][4], accB[2][2][4];
#pragma unroll
        for (int tm = 0; tm < 2; tm++)
#pragma unroll
            for (int tn = 0; tn < 2; tn++)
#pragma unroll
                for (int q = 0; q < 4; q++) { acc[tm][tn][q] = 0.0f; accB[tm][tn][q] = 0.0f; }

#pragma unroll 1
        for (int c = 0; c < 8; c++) {
            const int buf = c & 1;
            if (c < 7) {
                const int nb = buf ^ 1;
                const int kc = (c + 1) * 64;
#pragma unroll
                for (int i = 0; i < 2; i++) {
                    int idx = tx + i * 256;
                    int row = idx >> 3, gg = idx & 7;
                    uint32_t so = (uint32_t)row * (RPAD * 2) + (uint32_t)gg * 16;
                    size_t  go = (size_t)(b0 + row) * 512 + kc + gg * 8;
                    CP16(shb[nb] + so, hcF + go);
                }
                CP_COMMIT();
                CP_WAIT1();
            } else {
                CP_WAIT0();
            }
            __syncthreads();
            const uint32_t Sf_u = shb[buf];
#pragma unroll
            for (int k16 = 0; k16 < 64; k16 += 16) {
                uint32_t ah[2][4];
#pragma unroll
                for (int tm = 0; tm < 2; tm++) {
                    uint32_t aoff = (uint32_t)((m0w + tm * 16 + a_lrow) * RPAD + k16 + a_kof) * 2;
                    LDSM4(ah[tm][0], ah[tm][1], ah[tm][2], ah[tm][3], Sf_u + aoff);
                }
                const int kglob = c * 64 + k16 + b_kof;
                uint32_t bh[2][2], bl[2][2];
#pragma unroll
                for (int tn = 0; tn < 2; tn++) {
                    uint32_t boff = (uint32_t)((n0w + tn * 8 + b_lrow) * WPAD + kglob) * 2;
                    LDSM2(bh[tn][0], bh[tn][1], sWh_u + boff);
                    LDSM2(bl[tn][0], bl[tn][1], sWl_u + boff);
                }
#pragma unroll
                for (int tm = 0; tm < 2; tm++)
#pragma unroll
                    for (int tn = 0; tn < 2; tn++) {
                        MMAF16(acc[tm][tn],  ah[tm], bh[tn]);
                        MMAF16(accB[tm][tn], ah[tm], bl[tn]);
                    }
            }
            __syncthreads();
        }

        // publish gate preactivations: acc + accB*2^-11
#pragma unroll
        for (int tm = 0; tm < 2; tm++)
#pragma unroll
            for (int tn = 0; tn < 2; tn++) {
                int r = m0w + 16 * tm + g;
                int c0i = n0w + tn * 8 + 2 * tig;
                *(float2*)&sg[r * SGPAD + c0i] =
                    make_float2(acc[tm][tn][0] + accB[tm][tn][0] * WLSCALE,
                                acc[tm][tn][1] + accB[tm][tn][1] * WLSCALE);
                *(float2*)&sg[(r + 8) * SGPAD + c0i] =
                    make_float2(acc[tm][tn][2] + accB[tm][tn][2] * WLSCALE,
                                acc[tm][tn][3] + accB[tm][tn][3] * WLSCALE);
            }
        __syncthreads();

        // elementwise update
        {
            const float mcur = smk[ebr];
            const float mnxt = smk[64 + ebr];
            float hn[4];
#pragma unroll
            for (int i = 0; i < 4; i++) {
                int q = ekb + i;
                float vi = sg[ebr * SGPAD + q]      + gi_[i];
                float vf = sg[ebr * SGPAD + 16 + q] + gf_[i];
                float vg = sg[ebr * SGPAD + 32 + q] + gg_[i];
                float vo = sg[ebr * SGPAD + 48 + q] + go_[i];
                float cc = sc[ebr * 16 + q] * mcur;
                float cn = sigf(vf) * cc + sigf(vi) * ftanh(vg);
                hn[i] = sigf(vo) * ftanh(cn);
                sc[ebr * 16 + q] = cn;
            }
            // Y out: pi bf16 pair (precise), vf fp16 single
            size_t yo = ((size_t)eb * TT + t) * HH + hc0 + ekb;
            if (lstm == 0) {
                __nv_bfloat162 h01, h23, l01, l23;
                h01.x = __float2bfloat16_rn(hn[0]); h01.y = __float2bfloat16_rn(hn[1]);
                h23.x = __float2bfloat16_rn(hn[2]); h23.y = __float2bfloat16_rn(hn[3]);
                l01.x = __float2bfloat16_rn(hn[0] - __bfloat162float(h01.x));
                l01.y = __float2bfloat16_rn(hn[1] - __bfloat162float(h01.y));
                l23.x = __float2bfloat16_rn(hn[2] - __bfloat162float(h23.x));
                l23.y = __float2bfloat16_rn(hn[3] - __bfloat162float(h23.y));
                *(__nv_bfloat162*)(Yph + yo)     = h01;
                *(__nv_bfloat162*)(Yph + yo + 2) = h23;
                *(__nv_bfloat162*)(Ypl + yo)     = l01;
                *(__nv_bfloat162*)(Ypl + yo + 2) = l23;
            } else {
                __half2 y01, y23;
                y01.x = __float2half_rn(hn[0]); y01.y = __float2half_rn(hn[1]);
                y23.x = __float2half_rn(hn[2]); y23.y = __float2half_rn(hn[3]);
                *(__half2*)(Yv16 + yo)     = y01;
                *(__half2*)(Yv16 + yo + 2) = y23;
            }
            if (t + 1 < TT) {
                fp16* hnF = hfb + ((t + 1) & 1) * BB * HH;
                size_t ho = (size_t)eb * HH + hc0 + ekb;
                __half2 p01, p23;
                p01.x = __float2half_rn(hn[0] * mnxt); p01.y = __float2half_rn(hn[1] * mnxt);
                p23.x = __float2half_rn(hn[2] * mnxt); p23.y = __float2half_rn(hn[3] * mnxt);
                *(__half2*)(hnF + ho)     = p01;
                *(__half2*)(hnF + ho + 2) = p23;
            } else {
                float* oh = out + (size_t)3 * NR + (size_t)lstm * 2 * NR;
#pragma unroll
                for (int i = 0; i < 4; i++)
                    oh[eb * HH + hc0 + ekb + i] = hn[i];
            }
        }
        grid_bar_grp(grp, 32);
    }

    // final c -> out
    float* oc = out + (size_t)3 * NR + (size_t)lstm * 2 * NR + NR;
    for (int s = 0; s < 4; s++) {
        int idx = tx + s * 256;
        int br = idx >> 4, q = idx & 15;
        oc[(b0 + br) * HH + hc0 + q] = sc[br * 16 + q];
    }
}

// ---------------- heads ----------------
__global__ __launch_bounds__(128) void head_kernel(
    const float* __restrict__ Zpi, const float* __restrict__ Zvf,
    const float* __restrict__ aw, const float* __restrict__ ab,
    const float* __restrict__ cw, const float* __restrict__ cb,
    float* __restrict__ out)
{
    __shared__ float sx[512];
    __shared__ float slog[32];
    __shared__ float sval[4];
    const int n  = blockIdx.x;
    const int tx = threadIdx.x;

    ((float4*)sx)[tx] = ((const float4*)(Zpi + (size_t)n * 512))[tx];

    float4 xv = ((const float4*)(Zvf + (size_t)n * 512))[tx];
    float4 wv = ((const float4*)cw)[tx];
    float v = xv.x * wv.x + xv.y * wv.y + xv.z * wv.z + xv.w * wv.w;
#pragma unroll
    for (int off = 16; off; off >>= 1) v += __shfl_xor_sync(0xffffffffu, v, off);
    if ((tx & 31) == 0) sval[tx >> 5] = v;
    __syncthreads();

    const int l = tx >> 2;
    const int part = tx & 3;
    const float* wl = aw + l * 512 + part * 128;
    const float* xl = sx + part * 128;
    float s = 0.0f;
#pragma unroll 8
    for (int k4 = 0; k4 < 32; k4++) {
        float4 a = ((const float4*)xl)[k4];
        float4 w = ((const float4*)wl)[k4];
        s += a.x * w.x + a.y * w.y + a.z * w.z + a.w * w.w;
    }
    s += __shfl_xor_sync(0xffffffffu, s, 1);
    s += __shfl_xor_sync(0xffffffffu, s, 2);
    if (part == 0) slog[l] = s + ab[l];
    __syncthreads();

    if (tx < 32) {
        float lv = slog[tx];
        float m = lv; int mi = tx;
#pragma unroll
        for (int off = 16; off; off >>= 1) {
            float om = __shfl_xor_sync(0xffffffffu, m, off);
            int   oi = __shfl_xor_sync(0xffffffffu, mi, off);
            if (om > m || (om == m && oi < mi)) { m = om; mi = oi; }
        }
        float e = __expf(lv - m);
#pragma unroll
        for (int off = 16; off; off >>= 1) e += __shfl_xor_sync(0xffffffffu, e, off);
        if (tx == 0) {
            out[n] = (float)mi;
            out[(size_t)NR + n] = sval[0] + sval[1] + sval[2] + sval[3] + cb[0];
            out[(size_t)2 * NR + n] = -__logf(e);
        }
    }
}

// ---------------- launch ----------------
extern "C" void kernel_launch(void* const* d_in, const int* in_sizes, int n_in,
                              void* d_out, int out_size)
{
    const float* features = (const float*)d_in[0];
    const float* starts   = (const float*)d_in[1];
    const float* h0pi = (const float*)d_in[2];
    const float* c0pi = (const float*)d_in[3];
    const float* h0vf = (const float*)d_in[4];
    const float* c0vf = (const float*)d_in[5];
    const float* Wihpi = (const float*)d_in[6];
    const float* Whhpi = (const float*)d_in[7];
    const float* bihpi = (const float*)d_in[8];
    const float* bhhpi = (const float*)d_in[9];
    const float* Wihvf = (const float*)d_in[10];
    const float* Whhvf = (const float*)d_in[11];
    const float* bihvf = (const float*)d_in[12];
    const float* bhhvf = (const float*)d_in[13];
    const float* polw1 = (const float*)d_in[14];
    const float* polb1 = (const float*)d_in[15];
    const float* polw2 = (const float*)d_in[16];
    const float* polb2 = (const float*)d_in[17];
    const float* valw1 = (const float*)d_in[18];
    const float* valb1 = (const float*)d_in[19];
    const float* valw2 = (const float*)d_in[20];
    const float* valb2 = (const float*)d_in[21];
    const float* aw = (const float*)d_in[22];
    const float* ab = (const float*)d_in[23];
    const float* cw = (const float*)d_in[24];
    const float* cb = (const float*)d_in[25];

    float *Gpi, *Z2pi, *Z2vf;
    cudaGetSymbolAddress((void**)&Gpi,  g_Gpi);
    cudaGetSymbolAddress((void**)&Z2pi, g_Z2pi);
    cudaGetSymbolAddress((void**)&Z2vf, g_Z2vf);
    fp16 *Gvf16, *f16, *wvf16, *yv16, *z1v16, *wval16, *hf;
    cudaGetSymbolAddress((void**)&Gvf16, g_Gvf16);
    cudaGetSymbolAddress((void**)&f16,   g_feat16);
    cudaGetSymbolAddress((void**)&wvf16, g_wvf16);
    cudaGetSymbolAddress((void**)&yv16,  g_yvf16);
    cudaGetSymbolAddress((void**)&z1v16, g_z1v16);
    cudaGetSymbolAddress((void**)&wval16, g_wval16);
    cudaGetSymbolAddress((void**)&hf,    g_hf);
    bf16 *fh, *fl, *wpih, *wpil, *yph, *ypl, *z1ph, *z1pl, *wh, *wlp;
    cudaGetSymbolAddress((void**)&fh,   g_feat_h);
    cudaGetSymbolAddress((void**)&fl,   g_feat_l);
    cudaGetSymbolAddress((void**)&wpih, g_wpi_h);
    cudaGetSymbolAddress((void**)&wpil, g_wpi_l);
    cudaGetSymbolAddress((void**)&yph,  g_ypi_h);
    cudaGetSymbolAddress((void**)&ypl,  g_ypi_l);
    cudaGetSymbolAddress((void**)&z1ph, g_z1p_h);
    cudaGetSymbolAddress((void**)&z1pl, g_z1p_l);
    cudaGetSymbolAddress((void**)&wh,   g_w_h);
    cudaGetSymbolAddress((void**)&wlp,  g_w_l);
    float* out = (float*)d_out;

    size_t tg_smem   = (size_t)2 * STGB * sizeof(bf16);      // 81920
    size_t tg16_smem = (size_t)2 * 2 * MATB * sizeof(fp16);  // 40960
    cudaFuncSetAttribute((const void*)tgemm, cudaFuncAttributeMaxDynamicSharedMemorySize, (int)tg_smem);
    cudaFuncSetAttribute((const void*)lstm_recur, cudaFuncAttributeMaxDynamicSharedMemorySize, LSTM_SMEM);

    // converts: pi precise (bf16 pairs), vf fast (fp16 singles)
    cvt4<<<2048, 256>>>(features, fh, fl, (size_t)NR * DD / 4,
                        Wihpi, wpih, wpil, (size_t)G4 * DD / 4,
                        polw1, wh + WOFF_PW1, wlp + WOFF_PW1, (size_t)HH * HH / 4,
                        polw2, wh + WOFF_PW2, wlp + WOFF_PW2, (size_t)HH * HH / 4);
    cvt4h<<<2048, 256>>>(features, f16, (size_t)NR * DD / 4,
                         Wihvf, wvf16, (size_t)G4 * DD / 4,
                         valw1, wval16 + WOFF_VW1, (size_t)HH * HH / 4,
                         valw2, wval16 + WOFF_VW2, (size_t)HH * HH / 4);

    // input GEMMs: pi bf16 3-pass (fp32 G); vf fp16 1-pass (fp16 G)
    tgemm<<<dim3(G4 / 128, NR / 128), 256, tg_smem>>>(fh, fl, wpih, wpil,
                                                      bihpi, bhhpi, Gpi, nullptr, nullptr, G4, 0);
    tgemm16s<<<dim3(G4 / 128, NR / 128), 256, tg16_smem>>>(f16, wvf16, bihvf, bhhvf,
                                                           Gvf16, nullptr, G4, 0);

    // recurrence (fp16 2-pass, R12 proven; vf reads fp16 G, writes fp16 Y)
    lstm_recur<<<128, 256, LSTM_SMEM>>>(Gpi, Gvf16, starts, h0pi, c0pi, h0vf, c0vf,
                                        Whhpi, Whhvf, yph, ypl, yv16, hf, out);

    // pi MLP (precise bf16 3-pass)
    tgemm<<<dim3(HH / 128, NR / 128), 256, tg_smem>>>(yph, ypl, wh + WOFF_PW1, wlp + WOFF_PW1,
                                                      polb1, nullptr, nullptr, z1ph, z1pl, HH, 1);
    tgemm<<<dim3(HH / 128, NR / 128), 256, tg_smem>>>(z1ph, z1pl, wh + WOFF_PW2, wlp + WOFF_PW2,
                                                      polb2, nullptr, Z2pi, nullptr, nullptr, HH, 0);

    // vf MLP (fast fp16 1-pass)
    tgemm16s<<<dim3(HH / 128, NR / 128), 256, tg16_smem>>>(yv16, wval16 + WOFF_VW1, valb1, nullptr,
                                                           z1v16, nullptr, HH, 1);
    tgemm16s<<<dim3(HH / 128, NR / 128), 256, tg16_smem>>>(z1v16, wval16 + WOFF_VW2, valb2, nullptr,
                                                           nullptr, Z2vf, HH, 0);

    // heads
    head_kernel<<<NR, 128>>>(Z2pi, Z2vf, aw, ab, cw, cb, out);
}

// round 17
// speedup vs baseline: 1.2445x; 1.0039x over previous
#include <cuda_runtime.h>
#include <cuda_bf16.h>
#include <cuda_fp16.h>
#include <math.h>
#include <stdint.h>

// Problem constants
#define BB 128
#define TT 512
#define DD 512
#define HH 512
#define G4 2048
#define NR (BB*TT)
#define AA 32

typedef __nv_bfloat16 bf16;
typedef __half fp16;

// ---------------- scratch (device globals) ----------------
__device__ float g_Gpi[(size_t)NR * G4];                       // pi gates fp32 (precise)
__device__ __align__(16) fp16 g_Gvf16[(size_t)NR * G4];        // vf gates fp16
__device__ float g_Z2pi[(size_t)NR * HH];
__device__ float g_Z2vf[(size_t)NR * HH];
__device__ unsigned g_bar_count4[4];
__device__ unsigned g_bar_gen4[4];

// pi input GEMM (precise): bf16 pairs
__device__ __align__(16) bf16 g_feat_h[(size_t)NR * DD];
__device__ __align__(16) bf16 g_feat_l[(size_t)NR * DD];
__device__ __align__(16) bf16 g_wpi_h[(size_t)G4 * DD];
__device__ __align__(16) bf16 g_wpi_l[(size_t)G4 * DD];
// vf input GEMM (fast): fp16 singles
__device__ __align__(16) fp16 g_feat16[(size_t)NR * DD];
__device__ __align__(16) fp16 g_wvf16[(size_t)G4 * DD];
// pi MLP path (precise): bf16 pairs
__device__ __align__(16) bf16 g_ypi_h[(size_t)NR * HH];
__device__ __align__(16) bf16 g_ypi_l[(size_t)NR * HH];
__device__ __align__(16) bf16 g_z1p_h[(size_t)NR * HH];
__device__ __align__(16) bf16 g_z1p_l[(size_t)NR * HH];
// vf MLP path (fast): fp16 singles
__device__ __align__(16) fp16 g_yvf16[(size_t)NR * HH];
__device__ __align__(16) fp16 g_z1v16[(size_t)NR * HH];
// h ping-pong: single fp16 (pre-masked) — both LSTMs (R12 proven)
__device__ __align__(16) fp16 g_hf[2 * 2 * BB * HH];
// pol weights bf16 pairs; val weights fp16 singles
#define WOFF_PW1  0
#define WOFF_PW2  262144
#define WPTOT     524288
__device__ __align__(16) bf16 g_w_h[WPTOT];
__device__ __align__(16) bf16 g_w_l[WPTOT];
#define WOFF_VW1  0
#define WOFF_VW2  262144
__device__ __align__(16) fp16 g_wval16[524288];

__device__ __forceinline__ float sigf(float x) {
    return __fdividef(1.0f, 1.0f + __expf(-x));
}
__device__ __forceinline__ float ftanh(float x) {
    float e = __expf(2.0f * x);
    return 1.0f - __fdividef(2.0f, e + 1.0f);
}

// ---------------- PTX helpers ----------------
#define CP16(d, s) asm volatile("cp.async.cg.shared.global [%0], [%1], 16;" :: "r"(d), "l"(s) : "memory")
#define CP_COMMIT() asm volatile("cp.async.commit_group;" ::: "memory")
#define CP_WAIT0()  asm volatile("cp.async.wait_group 0;" ::: "memory")
#define CP_WAIT1()  asm volatile("cp.async.wait_group 1;" ::: "memory")

__device__ __forceinline__ uint32_t smem_u32(const void* p) {
    uint32_t a;
    asm("{ .reg .u64 t; cvta.to.shared.u64 t, %1; cvt.u32.u64 %0, t; }" : "=r"(a) : "l"(p));
    return a;
}

#define MMA16816(c, a, b) \
    asm volatile("mma.sync.aligned.m16n8k16.row.col.f32.bf16.bf16.f32 " \
        "{%0,%1,%2,%3}, {%4,%5,%6,%7}, {%8,%9}, {%0,%1,%2,%3};" \
        : "+f"((c)[0]), "+f"((c)[1]), "+f"((c)[2]), "+f"((c)[3]) \
        : "r"((a)[0]), "r"((a)[1]), "r"((a)[2]), "r"((a)[3]), "r"((b)[0]), "r"((b)[1]))

#define MMAF16(c, a, b) \
    asm volatile("mma.sync.aligned.m16n8k16.row.col.f32.f16.f16.f32 " \
        "{%0,%1,%2,%3}, {%4,%5,%6,%7}, {%8,%9}, {%0,%1,%2,%3};" \
        : "+f"((c)[0]), "+f"((c)[1]), "+f"((c)[2]), "+f"((c)[3]) \
        : "r"((a)[0]), "r"((a)[1]), "r"((a)[2]), "r"((a)[3]), "r"((b)[0]), "r"((b)[1]))

#define LDSM4(r0, r1, r2, r3, addr) \
    asm volatile("ldmatrix.sync.aligned.m8n8.x4.shared.b16 {%0,%1,%2,%3}, [%4];" \
        : "=r"(r0), "=r"(r1), "=r"(r2), "=r"(r3) : "r"(addr))
#define LDSM2(r0, r1, addr) \
    asm volatile("ldmatrix.sync.aligned.m8n8.x2.shared.b16 {%0,%1}, [%2];" \
        : "=r"(r0), "=r"(r1) : "r"(addr))

#define WLSCALE 4.8828125e-4f   // 2^-11

// ---------------- converters ----------------
__device__ __forceinline__ void cvt_one(const float* __restrict__ x,
                                        bf16* __restrict__ hi, bf16* __restrict__ lo, size_t i)
{
    float4 v = ((const float4*)x)[i];
    bf16 h0 = __float2bfloat16_rn(v.x), h1 = __float2bfloat16_rn(v.y);
    bf16 h2 = __float2bfloat16_rn(v.z), h3 = __float2bfloat16_rn(v.w);
    bf16 l0 = __float2bfloat16_rn(v.x - __bfloat162float(h0));
    bf16 l1 = __float2bfloat16_rn(v.y - __bfloat162float(h1));
    bf16 l2 = __float2bfloat16_rn(v.z - __bfloat162float(h2));
    bf16 l3 = __float2bfloat16_rn(v.w - __bfloat162float(h3));
    __nv_bfloat162 hp0; hp0.x = h0; hp0.y = h1;
    __nv_bfloat162 hp1; hp1.x = h2; hp1.y = h3;
    __nv_bfloat162 lp0; lp0.x = l0; lp0.y = l1;
    __nv_bfloat162 lp1; lp1.x = l2; lp1.y = l3;
    ((__nv_bfloat162*)hi)[2 * i]     = hp0;
    ((__nv_bfloat162*)hi)[2 * i + 1] = hp1;
    ((__nv_bfloat162*)lo)[2 * i]     = lp0;
    ((__nv_bfloat162*)lo)[2 * i + 1] = lp1;
}
__device__ __forceinline__ void cvt_one_h(const float* __restrict__ x,
                                          fp16* __restrict__ y, size_t i)
{
    float4 v = ((const float4*)x)[i];
    __half2 a, b;
    a.x = __float2half_rn(v.x); a.y = __float2half_rn(v.y);
    b.x = __float2half_rn(v.z); b.y = __float2half_rn(v.w);
    ((__half2*)y)[2 * i]     = a;
    ((__half2*)y)[2 * i + 1] = b;
}

// features -> bf16 pair + fp16 single in ONE read
__global__ __launch_bounds__(256) void cvt_feat(
    const float* __restrict__ x, bf16* __restrict__ hi, bf16* __restrict__ lo,
    fp16* __restrict__ f, size_t n4)
{
    for (size_t i = blockIdx.x * blockDim.x + threadIdx.x; i < n4; i += (size_t)gridDim.x * blockDim.x) {
        float4 v = ((const float4*)x)[i];
        bf16 h0 = __float2bfloat16_rn(v.x), h1 = __float2bfloat16_rn(v.y);
        bf16 h2 = __float2bfloat16_rn(v.z), h3 = __float2bfloat16_rn(v.w);
        __nv_bfloat162 hp0; hp0.x = h0; hp0.y = h1;
        __nv_bfloat162 hp1; hp1.x = h2; hp1.y = h3;
        __nv_bfloat162 lp0, lp1;
        lp0.x = __float2bfloat16_rn(v.x - __bfloat162float(h0));
        lp0.y = __float2bfloat16_rn(v.y - __bfloat162float(h1));
        lp1.x = __float2bfloat16_rn(v.z - __bfloat162float(h2));
        lp1.y = __float2bfloat16_rn(v.w - __bfloat162float(h3));
        ((__nv_bfloat162*)hi)[2 * i]     = hp0;
        ((__nv_bfloat162*)hi)[2 * i + 1] = hp1;
        ((__nv_bfloat162*)lo)[2 * i]     = lp0;
        ((__nv_bfloat162*)lo)[2 * i + 1] = lp1;
        __half2 a, b;
        a.x = __float2half_rn(v.x); a.y = __float2half_rn(v.y);
        b.x = __float2half_rn(v.z); b.y = __float2half_rn(v.w);
        ((__half2*)f)[2 * i]     = a;
        ((__half2*)f)[2 * i + 1] = b;
    }
}

// 3 bf16-pair conversions in one launch
__global__ __launch_bounds__(256) void cvt3(
    const float* __restrict__ x0, bf16* __restrict__ h0, bf16* __restrict__ l0, size_t n0,
    const float* __restrict__ x1, bf16* __restrict__ h1, bf16* __restrict__ l1, size_t n1,
    const float* __restrict__ x2, bf16* __restrict__ h2, bf16* __restrict__ l2, size_t n2)
{
    size_t tot = n0 + n1 + n2;
    for (size_t i = blockIdx.x * blockDim.x + threadIdx.x; i < tot; i += (size_t)gridDim.x * blockDim.x) {
        if (i < n0) cvt_one(x0, h0, l0, i);
        else if (i < n0 + n1) cvt_one(x1, h1, l1, i - n0);
        else cvt_one(x2, h2, l2, i - n0 - n1);
    }
}

// 3 fp16-single conversions in one launch
__global__ __launch_bounds__(256) void cvt3h(
    const float* __restrict__ x0, fp16* __restrict__ y0, size_t n0,
    const float* __restrict__ x1, fp16* __restrict__ y1, size_t n1,
    const float* __restrict__ x2, fp16* __restrict__ y2, size_t n2)
{
    size_t tot = n0 + n1 + n2;
    for (size_t i = blockIdx.x * blockDim.x + threadIdx.x; i < tot; i += (size_t)gridDim.x * blockDim.x) {
        if (i < n0) cvt_one_h(x0, y0, i);
        else if (i < n0 + n1) cvt_one_h(x1, y1, i - n0);
        else cvt_one_h(x2, y2, i - n0 - n1);
    }
}

// ---------------- HMMA bf16-split GEMM (pi path, proven) ----------------
#define KSTG 32
#define ROWP 40
#define MATB (128 * ROWP)
#define STGB (4 * MATB)
__global__ __launch_bounds__(256, 1) void tgemm(
    const bf16* __restrict__ Ah, const bf16* __restrict__ Al,
    const bf16* __restrict__ Wh, const bf16* __restrict__ Wl,
    const float* __restrict__ b1, const float* __restrict__ b2,
    float* __restrict__ C, bf16* __restrict__ Ch, bf16* __restrict__ Cl,
    int N, int relu)
{
    extern __shared__ bf16 smbf[];
    const int tid  = threadIdx.x;
    const int wid  = tid >> 5, lane = tid & 31;
    const int g    = lane >> 2, tig = lane & 3;
    const int m0   = (wid & 3) * 32;
    const int n0   = (wid >> 2) * 64;
    const size_t arow0 = (size_t)blockIdx.y * 128;
    const size_t brow0 = (size_t)blockIdx.x * 128;

    const int a_lrow = ((lane >> 3) & 1) * 8 + (lane & 7);
    const int a_kof  = (lane >> 4) * 8;
    const int b_lrow = lane & 7;
    const int b_kof  = ((lane >> 3) & 1) * 8;

    const int lmat = tid >> 6, t64 = tid & 63;
    const bf16* gsrc;
    if      (lmat == 0) gsrc = Ah + arow0 * 512;
    else if (lmat == 1) gsrc = Al + arow0 * 512;
    else if (lmat == 2) gsrc = Wh + brow0 * 512;
    else                gsrc = Wl + brow0 * 512;
    const uint32_t sbase = smem_u32(smbf);
    const uint32_t sdstm = sbase + (uint32_t)lmat * (MATB * 2);

    float acc[2][8][4];
#pragma unroll
    for (int i = 0; i < 2; i++)
#pragma unroll
        for (int j = 0; j < 8; j++)
#pragma unroll
            for (int q = 0; q < 4; q++) acc[i][j][q] = 0.0f;

#pragma unroll
    for (int s = 0; s < 2; s++) {
        const uint32_t db = sdstm + (uint32_t)s * (STGB * 2);
        const int k0 = s * KSTG;
#pragma unroll
        for (int i = 0; i < 8; i++) {
            int idx = i * 64 + t64;
            int row = idx >> 2, gg = idx & 3;
            CP16(db + (uint32_t)row * (ROWP * 2) + (uint32_t)gg * 16,
                 gsrc + (size_t)row * 512 + k0 + gg * 8);
        }
        CP_COMMIT();
    }

    const int NSTG = 512 / KSTG;
#pragma unroll 1
    for (int c = 0; c < NSTG; c++) {
        if (c < NSTG - 2) { CP_WAIT1(); } else { CP_WAIT0(); }
        __syncthreads();
        const uint32_t sS = sbase + (uint32_t)(c & 1) * (STGB * 2);
        const uint32_t sAh_u = sS;
        const uint32_t sAl_u = sS + MATB * 2;
        const uint32_t sWh_u = sS + 2 * MATB * 2;
        const uint32_t sWl_u = sS + 3 * MATB * 2;
#pragma unroll
        for (int kk = 0; kk < KSTG; kk += 16) {
            uint32_t ah[2][4], al[2][4];
#pragma unroll
            for (int tm = 0; tm < 2; tm++) {
                uint32_t aoff = (uint32_t)((m0 + tm * 16 + a_lrow) * ROWP + kk + a_kof) * 2;
                LDSM4(ah[tm][0], ah[tm][1], ah[tm][2], ah[tm][3], sAh_u + aoff);
                LDSM4(al[tm][0], al[tm][1], al[tm][2], al[tm][3], sAl_u + aoff);
            }
            uint32_t bh[8][2], bl[8][2];
#pragma unroll
            for (int tn = 0; tn < 8; tn++) {
                uint32_t boff = (uint32_t)((n0 + tn * 8 + b_lrow) * ROWP + kk + b_kof) * 2;
                LDSM2(bh[tn][0], bh[tn][1], sWh_u + boff);
                LDSM2(bl[tn][0], bl[tn][1], sWl_u + boff);
            }
#pragma unroll
            for (int tm = 0; tm < 2; tm++)
#pragma unroll
                for (int tn = 0; tn < 8; tn++) {
                    MMA16816(acc[tm][tn], ah[tm], bh[tn]);
                    MMA16816(acc[tm][tn], ah[tm], bl[tn]);
                    MMA16816(acc[tm][tn], al[tm], bh[tn]);
                }
        }
        __syncthreads();
        if (c + 2 < NSTG) {
            const uint32_t db = sdstm + (uint32_t)(c & 1) * (STGB * 2);
            const int k0 = (c + 2) * KSTG;
#pragma unroll
            for (int i = 0; i < 8; i++) {
                int idx = i * 64 + t64;
                int row = idx >> 2, gg = idx & 3;
                CP16(db + (uint32_t)row * (ROWP * 2) + (uint32_t)gg * 16,
                     gsrc + (size_t)row * 512 + k0 + gg * 8);
            }
            CP_COMMIT();
        }
    }

#pragma unroll
    for (int tn = 0; tn < 8; tn++) {
        int cc = (int)brow0 + n0 + tn * 8 + 2 * tig;
        float bv0 = b1[cc]     + (b2 ? b2[cc]     : 0.0f);
        float bv1 = b1[cc + 1] + (b2 ? b2[cc + 1] : 0.0f);
#pragma unroll
        for (int tm = 0; tm < 2; tm++) {
            size_t r0 = arow0 + m0 + tm * 16 + g;
            float v[4];
            v[0] = acc[tm][tn][0] + bv0;
            v[1] = acc[tm][tn][1] + bv1;
            v[2] = acc[tm][tn][2] + bv0;
            v[3] = acc[tm][tn][3] + bv1;
            if (relu) {
#pragma unroll
                for (int q = 0; q < 4; q++) v[q] = fmaxf(v[q], 0.f);
            }
            if (Ch) {
                __nv_bfloat162 h0, h1, l0, l1;
                h0.x = __float2bfloat16_rn(v[0]); h0.y = __float2bfloat16_rn(v[1]);
                h1.x = __float2bfloat16_rn(v[2]); h1.y = __float2bfloat16_rn(v[3]);
                l0.x = __float2bfloat16_rn(v[0] - __bfloat162float(h0.x));
                l0.y = __float2bfloat16_rn(v[1] - __bfloat162float(h0.y));
                l1.x = __float2bfloat16_rn(v[2] - __bfloat162float(h1.x));
                l1.y = __float2bfloat16_rn(v[3] - __bfloat162float(h1.y));
                *(__nv_bfloat162*)(Ch + r0 * (size_t)N + cc)       = h0;
                *(__nv_bfloat162*)(Cl + r0 * (size_t)N + cc)       = l0;
                *(__nv_bfloat162*)(Ch + (r0 + 8) * (size_t)N + cc) = h1;
                *(__nv_bfloat162*)(Cl + (r0 + 8) * (size_t)N + cc) = l1;
            } else {
                *(float2*)(C + r0 * (size_t)N + cc)       = make_float2(v[0], v[1]);
                *(float2*)(C + (r0 + 8) * (size_t)N + cc) = make_float2(v[2], v[3]);
            }
        }
    }
}

// ---------------- single-pass fp16 GEMM (vf path) ----------------
__global__ __launch_bounds__(256, 1) void tgemm16s(
    const fp16* __restrict__ A, const fp16* __restrict__ W,
    const float* __restrict__ b1, const float* __restrict__ b2,
    fp16* __restrict__ Cf16, float* __restrict__ Cf32,
    int N, int relu)
{
    extern __shared__ fp16 smh[];
    const int tid  = threadIdx.x;
    const int wid  = tid >> 5, lane = tid & 31;
    const int g    = lane >> 2, tig = lane & 3;
    const int m0   = (wid & 3) * 32;
    const int n0   = (wid >> 2) * 64;
    const size_t arow0 = (size_t)blockIdx.y * 128;
    const size_t brow0 = (size_t)blockIdx.x * 128;

    const int a_lrow = ((lane >> 3) & 1) * 8 + (lane & 7);
    const int a_kof  = (lane >> 4) * 8;
    const int b_lrow = lane & 7;
    const int b_kof  = ((lane >> 3) & 1) * 8;

    const uint32_t sbase = smem_u32(smh);
    const fp16* Ab = A + arow0 * 512;
    const fp16* Wb = W + brow0 * 512;

    float acc[2][8][4];
#pragma unroll
    for (int i = 0; i < 2; i++)
#pragma unroll
        for (int j = 0; j < 8; j++)
#pragma unroll
            for (int q = 0; q < 4; q++) acc[i][j][q] = 0.0f;

#pragma unroll
    for (int s = 0; s < 2; s++) {
        const uint32_t db = sbase + (uint32_t)s * (2 * MATB * 2);
        const int k0 = s * KSTG;
#pragma unroll
        for (int i = 0; i < 4; i++) {
            int idx = tid + i * 256;
            int mat = idx >> 9, g512 = idx & 511;
            int row = g512 >> 2, gg = g512 & 3;
            const fp16* src = (mat ? Wb : Ab) + (size_t)row * 512 + k0 + gg * 8;
            CP16(db + (uint32_t)mat * (MATB * 2) + (uint32_t)row * (ROWP * 2) + (uint32_t)gg * 16, src);
        }
        CP_COMMIT();
    }

    const int NSTG = 512 / KSTG;
#pragma unroll 1
    for (int c = 0; c < NSTG; c++) {
        if (c < NSTG - 2) { CP_WAIT1(); } else { CP_WAIT0(); }
        __syncthreads();
        const uint32_t sS = sbase + (uint32_t)(c & 1) * (2 * MATB * 2);
        const uint32_t sA_u = sS;
        const uint32_t sW_u = sS + MATB * 2;
#pragma unroll
        for (int kk = 0; kk < KSTG; kk += 16) {
            uint32_t ah[2][4];
#pragma unroll
            for (int tm = 0; tm < 2; tm++) {
                uint32_t aoff = (uint32_t)((m0 + tm * 16 + a_lrow) * ROWP + kk + a_kof) * 2;
                LDSM4(ah[tm][0], ah[tm][1], ah[tm][2], ah[tm][3], sA_u + aoff);
            }
            uint32_t bh[8][2];
#pragma unroll
            for (int tn = 0; tn < 8; tn++) {
                uint32_t boff = (uint32_t)((n0 + tn * 8 + b_lrow) * ROWP + kk + b_kof) * 2;
                LDSM2(bh[tn][0], bh[tn][1], sW_u + boff);
            }
#pragma unroll
            for (int tm = 0; tm < 2; tm++)
#pragma unroll
                for (int tn = 0; tn < 8; tn++)
                    MMAF16(acc[tm][tn], ah[tm], bh[tn]);
        }
        __syncthreads();
        if (c + 2 < NSTG) {
            const uint32_t db = sbase + (uint32_t)(c & 1) * (2 * MATB * 2);
            const int k0 = (c + 2) * KSTG;
#pragma unroll
            for (int i = 0; i < 4; i++) {
                int idx = tid + i * 256;
                int mat = idx >> 9, g512 = idx & 511;
                int row = g512 >> 2, gg = g512 & 3;
                const fp16* src = (mat ? Wb : Ab) + (size_t)row * 512 + k0 + gg * 8;
                CP16(db + (uint32_t)mat * (MATB * 2) + (uint32_t)row * (ROWP * 2) + (uint32_t)gg * 16, src);
            }
            CP_COMMIT();
        }
    }

#pragma unroll
    for (int tn = 0; tn < 8; tn++) {
        int cc = (int)brow0 + n0 + tn * 8 + 2 * tig;
        float bv0 = b1[cc]     + (b2 ? b2[cc]     : 0.0f);
        float bv1 = b1[cc + 1] + (b2 ? b2[cc + 1] : 0.0f);
#pragma unroll
        for (int tm = 0; tm < 2; tm++) {
            size_t r0 = arow0 + m0 + tm * 16 + g;
            float v[4];
            v[0] = acc[tm][tn][0] + bv0;
            v[1] = acc[tm][tn][1] + bv1;
            v[2] = acc[tm][tn][2] + bv0;
            v[3] = acc[tm][tn][3] + bv1;
            if (relu) {
#pragma unroll
                for (int q = 0; q < 4; q++) v[q] = fmaxf(v[q], 0.f);
            }
            if (Cf16) {
                __half2 v01, v23;
                v01.x = __float2half_rn(v[0]); v01.y = __float2half_rn(v[1]);
                v23.x = __float2half_rn(v[2]); v23.y = __float2half_rn(v[3]);
                *(__half2*)(Cf16 + r0 * (size_t)N + cc)       = v01;
                *(__half2*)(Cf16 + (r0 + 8) * (size_t)N + cc) = v23;
            } else {
                *(float2*)(Cf32 + r0 * (size_t)N + cc)       = make_float2(v[0], v[1]);
                *(float2*)(Cf32 + (r0 + 8) * (size_t)N + cc) = make_float2(v[2], v[3]);
            }
        }
    }
}

// ---------------- per-group software barrier ----------------
__device__ __forceinline__ void grid_bar_grp(int grp, int nct) {
    __threadfence();
    __syncthreads();
    if (threadIdx.x == 0) {
        volatile unsigned* vgen = &g_bar_gen4[grp];
        unsigned g = *vgen;
        unsigned a = atomicAdd(&g_bar_count4[grp], 1u);
        if (a == (unsigned)nct - 1u) {
            g_bar_count4[grp] = 0u;
            __threadfence();
            atomicAdd(&g_bar_gen4[grp], 1u);
        } else {
            while (*vgen == g) { }
        }
        __threadfence();
    }
    __syncthreads();
}

// ---------------- persistent recurrent kernel: fp16 2-pass (R15 proven) ----------------
#define RPAD 72
#define WPAD 520
#define SGPAD 72
#define HBUF (64 * RPAD * 2)
#define OFF_WH   0
#define OFF_WL   (64 * WPAD * 2)
#define OFF_HB0  (2 * 64 * WPAD * 2)
#define OFF_HB1  (OFF_HB0 + HBUF)
#define OFF_SG   (OFF_HB0 + 2 * HBUF)
#define OFF_MASK (OFF_SG + 64 * SGPAD * 4)
#define OFF_SC   (OFF_MASK + 128 * 4)
#define LSTM_SMEM (OFF_SC + 64 * 16 * 4)

__global__ __launch_bounds__(256, 1) void lstm_recur(
    const float* __restrict__ Gpi, const fp16* __restrict__ Gvf,
    const float* __restrict__ starts,
    const float* __restrict__ h0pi, const float* __restrict__ c0pi,
    const float* __restrict__ h0vf, const float* __restrict__ c0vf,
    const float* __restrict__ Whhpi, const float* __restrict__ Whhvf,
    bf16* __restrict__ Yph, bf16* __restrict__ Ypl,
    fp16* __restrict__ Yv16,
    fp16* __restrict__ hfg,
    float* __restrict__ out)
{
    extern __shared__ char sm8[];
    fp16*  sWh = (fp16*)(sm8 + OFF_WH);
    fp16*  sWl = (fp16*)(sm8 + OFF_WL);
    float* sg  = (float*)(sm8 + OFF_SG);
    float* smk = (float*)(sm8 + OFF_MASK);
    float* sc  = (float*)(sm8 + OFF_SC);

    const int ct   = blockIdx.x;
    const int lstm = ct >> 6;
    const int grp  = ct >> 5;
    const int b0   = ((ct >> 5) & 1) * 64;
    const int cid  = ct & 31;
    const int hc0  = cid * 16;
    const int tx   = threadIdx.x;
    const int wid  = tx >> 5, lane = tx & 31;
    const int g    = lane >> 2, tig = lane & 3;
    const int m0w  = (wid & 1) * 32;
    const int n0w  = (wid >> 1) * 16;

    const int a_lrow = ((lane >> 3) & 1) * 8 + (lane & 7);
    const int a_kof  = (lane >> 4) * 8;
    const int b_lrow = lane & 7;
    const int b_kof  = ((lane >> 3) & 1) * 8;

    const float* Whh = lstm ? Whhvf : Whhpi;
    const float* h0  = lstm ? h0vf  : h0pi;
    const float* c0  = lstm ? c0vf  : c0pi;
    fp16* hfb = hfg + lstm * 2 * BB * HH;

    const uint32_t sb = smem_u32(sm8);
    const uint32_t shb[2] = { sb + OFF_HB0, sb + OFF_HB1 };
    const uint32_t sWh_u = sb + OFF_WH;
    const uint32_t sWl_u = sb + OFF_WL;

    // load + split Whh slice (fp16 hi + scaled lo)
    for (int s = 0; s < 128; s++) {
        int idx = tx + s * 256;
        int j = idx >> 9, k = idx & 511;
        int gc = ((j >> 4) << 9) + hc0 + (j & 15);
        float w = Whh[(size_t)gc * HH + k];
        fp16 hi = __float2half_rn(w);
        sWh[j * WPAD + k] = hi;
        sWl[j * WPAD + k] = __float2half_rn((w - __half2float(hi)) * 2048.0f);
    }
    // init c and h0 (ping 0, pre-masked, fp16)
    for (int s = 0; s < 4; s++) {
        int idx = tx + s * 256;
        int br = idx >> 4, q = idx & 15;
        int b = b0 + br;
        sc[br * 16 + q] = c0[b * HH + hc0 + q];
        float m0 = 1.0f - starts[b * TT];
        hfb[b * HH + hc0 + q] = __float2half_rn(h0[b * HH + hc0 + q] * m0);
    }
    grid_bar_grp(grp, 32);

    const int ebr = tx >> 2;
    const int ekb = (tx & 3) << 2;
    const int eb  = b0 + ebr;

    for (int t = 0; t < TT; t++) {
        const int cur = t & 1;
        const fp16* hcF = hfb + cur * BB * HH;

        // G prefetch for this step (pi: fp32; vf: fp16)
        const size_t grow = ((size_t)eb * TT + t) * G4 + hc0 + ekb;
        float gi_[4], gf_[4], gg_[4], go_[4];
        if (lstm == 0) {
            const float4 a = *(const float4*)(Gpi + grow);
            const float4 b = *(const float4*)(Gpi + grow + 512);
            const float4 c = *(const float4*)(Gpi + grow + 1024);
            const float4 d = *(const float4*)(Gpi + grow + 1536);
            gi_[0]=a.x; gi_[1]=a.y; gi_[2]=a.z; gi_[3]=a.w;
            gf_[0]=b.x; gf_[1]=b.y; gf_[2]=b.z; gf_[3]=b.w;
            gg_[0]=c.x; gg_[1]=c.y; gg_[2]=c.z; gg_[3]=c.w;
            go_[0]=d.x; go_[1]=d.y; go_[2]=d.z; go_[3]=d.w;
        } else {
            __half2 a0 = *(const __half2*)(Gvf + grow),        a1 = *(const __half2*)(Gvf + grow + 2);
            __half2 b0h = *(const __half2*)(Gvf + grow + 512),  b1h = *(const __half2*)(Gvf + grow + 514);
            __half2 c0h = *(const __half2*)(Gvf + grow + 1024), c1h = *(const __half2*)(Gvf + grow + 1026);
            __half2 d0 = *(const __half2*)(Gvf + grow + 1536), d1 = *(const __half2*)(Gvf + grow + 1538);
            gi_[0]=__half2float(a0.x); gi_[1]=__half2float(a0.y); gi_[2]=__half2float(a1.x); gi_[3]=__half2float(a1.y);
            gf_[0]=__half2float(b0h.x); gf_[1]=__half2float(b0h.y); gf_[2]=__half2float(b1h.x); gf_[3]=__half2float(b1h.y);
            gg_[0]=__half2float(c0h.x); gg_[1]=__half2float(c0h.y); gg_[2]=__half2float(c1h.x); gg_[3]=__half2float(c1h.y);
            go_[0]=__half2float(d0.x); go_[1]=__half2float(d0.y); go_[2]=__half2float(d1.x); go_[3]=__half2float(d1.y);
        }

        // prefetch h chunk 0 (K 0..63): 512 granules of 16B, 2 per thread
#pragma unroll
        for (int i = 0; i < 2; i++) {
            int idx = tx + i * 256;
            int row = idx >> 3, gg = idx & 7;
            uint32_t so = (uint32_t)row * (RPAD * 2) + (uint32_t)gg * 16;
            size_t  go = (size_t)(b0 + row) * 512 + gg * 8;
            CP16(shb[0] + so, hcF + go);
        }
        CP_COMMIT();

        // masks
        if (tx < 64) smk[tx] = 1.0f - starts[(b0 + tx) * TT + t];
        else if (tx < 128) {
            int br = tx - 64;
            smk[64 + br] = (t + 1 < TT) ? (1.0f - starts[(b0 + br) * TT + t + 1]) : 1.0f;
        }

        float acc[2][2][4], accB[2][2][4];
#pragma unroll
        for (int tm = 0; tm < 2; tm++)
#pragma unroll
            for (int tn = 0; tn < 2; tn++)
#pragma unroll
                for (int q = 0; q < 4; q++) { acc[tm][tn][q] = 0.0f; accB[tm][tn][q] = 0.0f; }

#pragma unroll 1
        for (int c = 0; c < 8; c++) {
            const int buf = c & 1;
            if (c < 7) {
                const int nb = buf ^ 1;
                const int kc = (c + 1) * 64;
#pragma unroll
                for (int i = 0; i < 2; i++) {
                    int idx = tx + i * 256;
                    int row = idx >> 3, gg = idx & 7;
                    uint32_t so = (uint32_t)row * (RPAD * 2) + (uint32_t)gg * 16;
                    size_t  go = (size_t)(b0 + row) * 512 + kc + gg * 8;
                    CP16(shb[nb] + so, hcF + go);
                }
                CP_COMMIT();
                CP_WAIT1();
            } else {
                CP_WAIT0();
            }
            __syncthreads();
            const uint32_t Sf_u = shb[buf];
#pragma unroll
            for (int k16 = 0; k16 < 64; k16 += 16) {
                uint32_t ah[2][4];
#pragma unroll
                for (int tm = 0; tm < 2; tm++) {
                    uint32_t aoff = (uint32_t)((m0w + tm * 16 + a_lrow) * RPAD + k16 + a_kof) * 2;
                    LDSM4(ah[tm][0], ah[tm][1], ah[tm][2], ah[tm][3], Sf_u + aoff);
                }
                const int kglob = c * 64 + k16 + b_kof;
                uint32_t bh[2][2], bl[2][2];
#pragma unroll
                for (int tn = 0; tn < 2; tn++) {
                    uint32_t boff = (uint32_t)((n0w + tn * 8 + b_lrow) * WPAD + kglob) * 2;
                    LDSM2(bh[tn][0], bh[tn][1], sWh_u + boff);
                    LDSM2(bl[tn][0], bl[tn][1], sWl_u + boff);
                }
#pragma unroll
                for (int tm = 0; tm < 2; tm++)
#pragma unroll
                    for (int tn = 0; tn < 2; tn++) {
                        MMAF16(acc[tm][tn],  ah[tm], bh[tn]);
                        MMAF16(accB[tm][tn], ah[tm], bl[tn]);
                    }
            }
            __syncthreads();
        }

        // publish gate preactivations: acc + accB*2^-11
#pragma unroll
        for (int tm = 0; tm < 2; tm++)
#pragma unroll
            for (int tn = 0; tn < 2; tn++) {
                int r = m0w + 16 * tm + g;
                int c0i = n0w + tn * 8 + 2 * tig;
                *(float2*)&sg[r * SGPAD + c0i] =
                    make_float2(acc[tm][tn][0] + accB[tm][tn][0] * WLSCALE,
                                acc[tm][tn][1] + accB[tm][tn][1] * WLSCALE);
                *(float2*)&sg[(r + 8) * SGPAD + c0i] =
                    make_float2(acc[tm][tn][2] + accB[tm][tn][2] * WLSCALE,
                                acc[tm][tn][3] + accB[tm][tn][3] * WLSCALE);
            }
        __syncthreads();

        // elementwise update
        {
            const float mcur = smk[ebr];
            const float mnxt = smk[64 + ebr];
            float hn[4];
#pragma unroll
            for (int i = 0; i < 4; i++) {
                int q = ekb + i;
                float vi = sg[ebr * SGPAD + q]      + gi_[i];
                float vf = sg[ebr * SGPAD + 16 + q] + gf_[i];
                float vg = sg[ebr * SGPAD + 32 + q] + gg_[i];
                float vo = sg[ebr * SGPAD + 48 + q] + go_[i];
                float cc = sc[ebr * 16 + q] * mcur;
                float cn = sigf(vf) * cc + sigf(vi) * ftanh(vg);
                hn[i] = sigf(vo) * ftanh(cn);
                sc[ebr * 16 + q] = cn;
            }
            // Y out: pi bf16 pair (precise), vf fp16 single
            size_t yo = ((size_t)eb * TT + t) * HH + hc0 + ekb;
            if (lstm == 0) {
                __nv_bfloat162 h01, h23, l01, l23;
                h01.x = __float2bfloat16_rn(hn[0]); h01.y = __float2bfloat16_rn(hn[1]);
                h23.x = __float2bfloat16_rn(hn[2]); h23.y = __float2bfloat16_rn(hn[3]);
                l01.x = __float2bfloat16_rn(hn[0] - __bfloat162float(h01.x));
                l01.y = __float2bfloat16_rn(hn[1] - __bfloat162float(h01.y));
                l23.x = __float2bfloat16_rn(hn[2] - __bfloat162float(h23.x));
                l23.y = __float2bfloat16_rn(hn[3] - __bfloat162float(h23.y));
                *(__nv_bfloat162*)(Yph + yo)     = h01;
                *(__nv_bfloat162*)(Yph + yo + 2) = h23;
                *(__nv_bfloat162*)(Ypl + yo)     = l01;
                *(__nv_bfloat162*)(Ypl + yo + 2) = l23;
            } else {
                __half2 y01, y23;
                y01.x = __float2half_rn(hn[0]); y01.y = __float2half_rn(hn[1]);
                y23.x = __float2half_rn(hn[2]); y23.y = __float2half_rn(hn[3]);
                *(__half2*)(Yv16 + yo)     = y01;
                *(__half2*)(Yv16 + yo + 2) = y23;
            }
            if (t + 1 < TT) {
                fp16* hnF = hfb + ((t + 1) & 1) * BB * HH;
                size_t ho = (size_t)eb * HH + hc0 + ekb;
                __half2 p01, p23;
                p01.x = __float2half_rn(hn[0] * mnxt); p01.y = __float2half_rn(hn[1] * mnxt);
                p23.x = __float2half_rn(hn[2] * mnxt); p23.y = __float2half_rn(hn[3] * mnxt);
                *(__half2*)(hnF + ho)     = p01;
                *(__half2*)(hnF + ho + 2) = p23;
            } else {
                float* oh = out + (size_t)3 * NR + (size_t)lstm * 2 * NR;
#pragma unroll
                for (int i = 0; i < 4; i++)
                    oh[eb * HH + hc0 + ekb + i] = hn[i];
            }
        }
        grid_bar_grp(grp, 32);
    }

    // final c -> out
    float* oc = out + (size_t)3 * NR + (size_t)lstm * 2 * NR + NR;
    for (int s = 0; s < 4; s++) {
        int idx = tx + s * 256;
        int br = idx >> 4, q = idx & 15;
        oc[(b0 + br) * HH + hc0 + q] = sc[br * 16 + q];
    }
}

// ---------------- heads: 2 rows per block, 256 threads ----------------
__global__ __launch_bounds__(256) void head_kernel(
    const float* __restrict__ Zpi, const float* __restrict__ Zvf,
    const float* __restrict__ aw, const float* __restrict__ ab,
    const float* __restrict__ cw, const float* __restrict__ cb,
    float* __restrict__ out)
{
    __shared__ float sx[2][512];
    __shared__ float slog[2][32];
    __shared__ float sval[2][4];
    const int half = threadIdx.x >> 7;      // 0/1: which row
    const int tx   = threadIdx.x & 127;
    const int n    = blockIdx.x * 2 + half;

    ((float4*)sx[half])[tx] = ((const float4*)(Zpi + (size_t)n * 512))[tx];

    float4 xv = ((const float4*)(Zvf + (size_t)n * 512))[tx];
    float4 wv = ((const float4*)cw)[tx];
    float v = xv.x * wv.x + xv.y * wv.y + xv.z * wv.z + xv.w * wv.w;
#pragma unroll
    for (int off = 16; off; off >>= 1) v += __shfl_xor_sync(0xffffffffu, v, off);
    if ((tx & 31) == 0) sval[half][tx >> 5] = v;
    __syncthreads();

    const int l = tx >> 2;
    const int part = tx & 3;
    const float* wl = aw + l * 512 + part * 128;
    const float* xl = sx[half] + part * 128;
    float s = 0.0f;
#pragma unroll 8
    for (int k4 = 0; k4 < 32; k4++) {
        float4 a = ((const float4*)xl)[k4];
        float4 w = ((const float4*)wl)[k4];
        s += a.x * w.x + a.y * w.y + a.z * w.z + a.w * w.w;
    }
    s += __shfl_xor_sync(0xffffffffu, s, 1);
    s += __shfl_xor_sync(0xffffffffu, s, 2);
    if (part == 0) slog[half][l] = s + ab[l];
    __syncthreads();

    if (tx < 32) {
        float lv = slog[half][tx];
        float m = lv; int mi = tx;
#pragma unroll
        for (int off = 16; off; off >>= 1) {
            float om = __shfl_xor_sync(0xffffffffu, m, off);
            int   oi = __shfl_xor_sync(0xffffffffu, mi, off);
            if (om > m || (om == m && oi < mi)) { m = om; mi = oi; }
        }
        float e = __expf(lv - m);
#pragma unroll
        for (int off = 16; off; off >>= 1) e += __shfl_xor_sync(0xffffffffu, e, off);
        if (tx == 0) {
            out[n] = (float)mi;
            out[(size_t)NR + n] = sval[half][0] + sval[half][1] + sval[half][2] + sval[half][3] + cb[0];
            out[(size_t)2 * NR + n] = -__logf(e);
        }
    }
}

// ---------------- launch ----------------
extern "C" void kernel_launch(void* const* d_in, const int* in_sizes, int n_in,
                              void* d_out, int out_size)
{
    const float* features = (const float*)d_in[0];
    const float* starts   = (const float*)d_in[1];
    const float* h0pi = (const float*)d_in[2];
    const float* c0pi = (const float*)d_in[3];
    const float* h0vf = (const float*)d_in[4];
    const float* c0vf = (const float*)d_in[5];
    const float* Wihpi = (const float*)d_in[6];
    const float* Whhpi = (const float*)d_in[7];
    const float* bihpi = (const float*)d_in[8];
    const float* bhhpi = (const float*)d_in[9];
    const float* Wihvf = (const float*)d_in[10];
    const float* Whhvf = (const float*)d_in[11];
    const float* bihvf = (const float*)d_in[12];
    const float* bhhvf = (const float*)d_in[13];
    const float* polw1 = (const float*)d_in[14];
    const float* polb1 = (const float*)d_in[15];
    const float* polw2 = (const float*)d_in[16];
    const float* polb2 = (const float*)d_in[17];
    const float* valw1 = (const float*)d_in[18];
    const float* valb1 = (const float*)d_in[19];
    const float* valw2 = (const float*)d_in[20];
    const float* valb2 = (const float*)d_in[21];
    const float* aw = (const float*)d_in[22];
    const float* ab = (const float*)d_in[23];
    const float* cw = (const float*)d_in[24];
    const float* cb = (const float*)d_in[25];

    float *Gpi, *Z2pi, *Z2vf;
    cudaGetSymbolAddress((void**)&Gpi,  g_Gpi);
    cudaGetSymbolAddress((void**)&Z2pi, g_Z2pi);
    cudaGetSymbolAddress((void**)&Z2vf, g_Z2vf);
    fp16 *Gvf16, *f16, *wvf16, *yv16, *z1v16, *wval16, *hf;
    cudaGetSymbolAddress((void**)&Gvf16, g_Gvf16);
    cudaGetSymbolAddress((void**)&f16,   g_feat16);
    cudaGetSymbolAddress((void**)&wvf16, g_wvf16);
    cudaGetSymbolAddress((void**)&yv16,  g_yvf16);
    cudaGetSymbolAddress((void**)&z1v16, g_z1v16);
    cudaGetSymbolAddress((void**)&wval16, g_wval16);
    cudaGetSymbolAddress((void**)&hf,    g_hf);
    bf16 *fh, *fl, *wpih, *wpil, *yph, *ypl, *z1ph, *z1pl, *wh, *wlp;
    cudaGetSymbolAddress((void**)&fh,   g_feat_h);
    cudaGetSymbolAddress((void**)&fl,   g_feat_l);
    cudaGetSymbolAddress((void**)&wpih, g_wpi_h);
    cudaGetSymbolAddress((void**)&wpil, g_wpi_l);
    cudaGetSymbolAddress((void**)&yph,  g_ypi_h);
    cudaGetSymbolAddress((void**)&ypl,  g_ypi_l);
    cudaGetSymbolAddress((void**)&z1ph, g_z1p_h);
    cudaGetSymbolAddress((void**)&z1pl, g_z1p_l);
    cudaGetSymbolAddress((void**)&wh,   g_w_h);
    cudaGetSymbolAddress((void**)&wlp,  g_w_l);
    float* out = (float*)d_out;

    size_t tg_smem   = (size_t)2 * STGB * sizeof(bf16);      // 81920
    size_t tg16_smem = (size_t)2 * 2 * MATB * sizeof(fp16);  // 40960
    cudaFuncSetAttribute((const void*)tgemm, cudaFuncAttributeMaxDynamicSharedMemorySize, (int)tg_smem);
    cudaFuncSetAttribute((const void*)lstm_recur, cudaFuncAttributeMaxDynamicSharedMemorySize, LSTM_SMEM);

    // converts: features (one read -> bf16 pair + fp16 single); weights
    cvt_feat<<<2048, 256>>>(features, fh, fl, f16, (size_t)NR * DD / 4);
    cvt3<<<512, 256>>>(Wihpi, wpih, wpil, (size_t)G4 * DD / 4,
                       polw1, wh + WOFF_PW1, wlp + WOFF_PW1, (size_t)HH * HH / 4,
                       polw2, wh + WOFF_PW2, wlp + WOFF_PW2, (size_t)HH * HH / 4);
    cvt3h<<<512, 256>>>(Wihvf, wvf16, (size_t)G4 * DD / 4,
                        valw1, wval16 + WOFF_VW1, (size_t)HH * HH / 4,
                        valw2, wval16 + WOFF_VW2, (size_t)HH * HH / 4);

    // input GEMMs: pi bf16 3-pass (fp32 G); vf fp16 1-pass (fp16 G)
    tgemm<<<dim3(G4 / 128, NR / 128), 256, tg_smem>>>(fh, fl, wpih, wpil,
                                                      bihpi, bhhpi, Gpi, nullptr, nullptr, G4, 0);
    tgemm16s<<<dim3(G4 / 128, NR / 128), 256, tg16_smem>>>(f16, wvf16, bihvf, bhhvf,
                                                           Gvf16, nullptr, G4, 0);

    // recurrence (fp16 2-pass; vf reads fp16 G, writes fp16 Y)
    lstm_recur<<<128, 256, LSTM_SMEM>>>(Gpi, Gvf16, starts, h0pi, c0pi, h0vf, c0vf,
                                        Whhpi, Whhvf, yph, ypl, yv16, hf, out);

    // pi MLP (precise bf16 3-pass)
    tgemm<<<dim3(HH / 128, NR / 128), 256, tg_smem>>>(yph, ypl, wh + WOFF_PW1, wlp + WOFF_PW1,
                                                      polb1, nullptr, nullptr, z1ph, z1pl, HH, 1);
    tgemm<<<dim3(HH / 128, NR / 128), 256, tg_smem>>>(z1ph, z1pl, wh + WOFF_PW2, wlp + WOFF_PW2,
                                                      polb2, nullptr, Z2pi, nullptr, nullptr, HH, 0);

    // vf MLP (fast fp16 1-pass)
    tgemm16s<<<dim3(HH / 128, NR / 128), 256, tg16_smem>>>(yv16, wval16 + WOFF_VW1, valb1, nullptr,
                                                           z1v16, nullptr, HH, 1);
    tgemm16s<<<dim3(HH / 128, NR / 128), 256, tg16_smem>>>(z1v16, wval16 + WOFF_VW2, valb2, nullptr,
                                                           nullptr, Z2vf, HH, 0);

    // heads (2 rows/block)
    head_kernel<<<NR / 2, 256>>>(Z2pi, Z2vf, aw, ab, cw, cb, out);
}